// round 4
// baseline (speedup 1.0000x reference)
#include <cuda_runtime.h>
#include <math.h>

#define T_TOK 4096
#define SEQ   2048
#define DRES  1024
#define D3    3072
#define DMLP  4096
#define NH    16

// ---------------- device scratch (allocation-free rule: __device__ globals) ----
__device__ float g_x[(size_t)T_TOK * DRES];        // ln output (reused for ln1 & ln2)
__device__ float g_qkv[(size_t)T_TOK * D3];        // [t, 3072]: Q | K | V, each head-major
__device__ float g_Wqkv[(size_t)DRES * D3];        // repacked [K=1024, N=3072]
__device__ float g_bqkv[D3];
__device__ float g_z[(size_t)T_TOK * DRES];        // attention out [t, h*64+e]
__device__ float g_rm[(size_t)T_TOK * DRES];       // resid_mid
__device__ float g_mlp[(size_t)T_TOK * DMLP];      // mlp hidden (post-gelu)

// ---------------- repack QKV weights into one [1024,3072] row-major B ---------
__global__ __launch_bounds__(256) void repack_kernel(
    const float* __restrict__ WQ, const float* __restrict__ WK,
    const float* __restrict__ WV, const float* __restrict__ bQ,
    const float* __restrict__ bK, const float* __restrict__ bV)
{
    int idx = blockIdx.x * 256 + threadIdx.x;
    if (idx < D3) {
        g_bqkv[idx] = (idx < 1024) ? bQ[idx]
                    : (idx < 2048) ? bK[idx - 1024]
                    :                bV[idx - 2048];
    }
    if (idx >= DRES * D3) return;
    int d = idx / D3;
    int j = idx % D3;
    const float* W = WQ; int jj = j;
    if (j >= 2048)      { W = WV; jj = j - 2048; }
    else if (j >= 1024) { W = WK; jj = j - 1024; }
    // W layout: [h, d, e] -> h*65536 + d*64 + e
    g_Wqkv[idx] = W[((jj >> 6) << 16) + (d << 6) + (jj & 63)];
}

// ---------------- layernorm: one block per row of 1024 ------------------------
__global__ __launch_bounds__(256) void ln_kernel(
    const float* __restrict__ x, const float* __restrict__ w,
    const float* __restrict__ b, float* __restrict__ y)
{
    __shared__ float red[8];
    __shared__ float sMean, sRstd;
    int row = blockIdx.x, tid = threadIdx.x;
    const float* xr = x + (size_t)row * DRES;
    float4 v = ((const float4*)xr)[tid];

    float s = v.x + v.y + v.z + v.w;
    #pragma unroll
    for (int o = 16; o > 0; o >>= 1) s += __shfl_xor_sync(0xffffffffu, s, o);
    if ((tid & 31) == 0) red[tid >> 5] = s;
    __syncthreads();
    if (tid == 0) {
        float t = 0.f;
        #pragma unroll
        for (int i = 0; i < 8; i++) t += red[i];
        sMean = t * (1.f / DRES);
    }
    __syncthreads();
    float mean = sMean;
    float cx = v.x - mean, cy = v.y - mean, cz = v.z - mean, cw = v.w - mean;
    float sq = cx * cx + cy * cy + cz * cz + cw * cw;
    #pragma unroll
    for (int o = 16; o > 0; o >>= 1) sq += __shfl_xor_sync(0xffffffffu, sq, o);
    if ((tid & 31) == 0) red[tid >> 5] = sq;
    __syncthreads();
    if (tid == 0) {
        float t = 0.f;
        #pragma unroll
        for (int i = 0; i < 8; i++) t += red[i];
        sRstd = rsqrtf(t * (1.f / DRES) + 1e-5f);
    }
    __syncthreads();
    float rstd = sRstd;
    float4 wv = ((const float4*)w)[tid];
    float4 bv = ((const float4*)b)[tid];
    float4 o;
    o.x = cx * rstd * wv.x + bv.x;
    o.y = cy * rstd * wv.y + bv.y;
    o.z = cz * rstd * wv.z + bv.z;
    o.w = cw * rstd * wv.w + bv.w;
    ((float4*)(y + (size_t)row * DRES))[tid] = o;
}

// ---------------- generic SGEMM 128x128x16, 256 threads, 8x8 microtile --------
// C[M,N] = A[M,K] @ B[K,N] + bias[N]  (+residual | gelu)
// mode: 0 = bias, 1 = bias + residual, 2 = bias + exact gelu
__device__ __forceinline__ float gelu_exact(float x) {
    return 0.5f * x * (1.0f + erff(x * 0.70710678118654752f));
}

__global__ __launch_bounds__(256) void sgemm_kernel(
    const float* __restrict__ A, const float* __restrict__ B,
    const float* __restrict__ bias, const float* __restrict__ res,
    float* __restrict__ C, int M, int N, int K, int mode)
{
    __shared__ float As[16 * 128];   // [k][m] transposed
    __shared__ float Bs[16 * 128];   // [k][n]
    int tid = threadIdx.x;
    int tx = tid & 15, ty = tid >> 4;
    int m0 = blockIdx.y * 128, n0 = blockIdx.x * 128;

    const float* Aptr = A + (size_t)m0 * K;
    const float* Bptr = B + n0;

    int arow = tid >> 2;   // 0..63
    int akq  = tid & 3;    // float4 index along K
    int brow = tid >> 5;   // 0..7
    int bcol = tid & 31;   // float4 index along N

    float acc[8][8];
    #pragma unroll
    for (int i = 0; i < 8; i++)
        #pragma unroll
        for (int j = 0; j < 8; j++) acc[i][j] = 0.f;

    for (int kt = 0; kt < K; kt += 16) {
        #pragma unroll
        for (int u = 0; u < 2; u++) {
            int r = arow + u * 64;
            float4 a = *(const float4*)(Aptr + (size_t)r * K + kt + akq * 4);
            As[(akq * 4 + 0) * 128 + r] = a.x;
            As[(akq * 4 + 1) * 128 + r] = a.y;
            As[(akq * 4 + 2) * 128 + r] = a.z;
            As[(akq * 4 + 3) * 128 + r] = a.w;
        }
        #pragma unroll
        for (int u = 0; u < 2; u++) {
            int kr = brow + u * 8;
            float4 bv = *(const float4*)(Bptr + (size_t)(kt + kr) * N + bcol * 4);
            *(float4*)&Bs[kr * 128 + bcol * 4] = bv;
        }
        __syncthreads();
        #pragma unroll
        for (int k = 0; k < 16; k++) {
            float a[8], b[8];
            *(float4*)(a)     = *(const float4*)&As[k * 128 + ty * 8];
            *(float4*)(a + 4) = *(const float4*)&As[k * 128 + ty * 8 + 4];
            *(float4*)(b)     = *(const float4*)&Bs[k * 128 + tx * 8];
            *(float4*)(b + 4) = *(const float4*)&Bs[k * 128 + tx * 8 + 4];
            #pragma unroll
            for (int i = 0; i < 8; i++)
                #pragma unroll
                for (int j = 0; j < 8; j++)
                    acc[i][j] = fmaf(a[i], b[j], acc[i][j]);
        }
        __syncthreads();
    }

    #pragma unroll
    for (int i = 0; i < 8; i++) {
        int row = m0 + ty * 8 + i;
        #pragma unroll
        for (int jq = 0; jq < 2; jq++) {
            int col = n0 + tx * 8 + jq * 4;
            float4 v;
            v.x = acc[i][jq * 4 + 0];
            v.y = acc[i][jq * 4 + 1];
            v.z = acc[i][jq * 4 + 2];
            v.w = acc[i][jq * 4 + 3];
            float4 bb = *(const float4*)(bias + col);
            v.x += bb.x; v.y += bb.y; v.z += bb.z; v.w += bb.w;
            if (mode == 1) {
                float4 r = *(const float4*)(res + (size_t)row * N + col);
                v.x += r.x; v.y += r.y; v.z += r.z; v.w += r.w;
            } else if (mode == 2) {
                v.x = gelu_exact(v.x); v.y = gelu_exact(v.y);
                v.z = gelu_exact(v.z); v.w = gelu_exact(v.w);
            }
            *(float4*)(C + (size_t)row * N + col) = v;
        }
    }
}

// ---------------- flash attention: 64-query tile, online softmax --------------
// qkv: [t, 3072], q = cols [h*64, h*64+64), k = +1024, v = +2048
// z out: [t, h*64+e]
__global__ __launch_bounds__(256) void attn_kernel(
    const float* __restrict__ qkv, float* __restrict__ z)
{
    __shared__ float Qt[64 * 64];   // e-major: Qt[e*64 + r], pre-scaled by 1/8
    __shared__ float KP[64 * 64];   // Kt[e*64 + c]  /  reused as P[r*64 + c]
    __shared__ float Vs[64 * 64];   // Vs[k*64 + e]
    int q0 = blockIdx.x << 6;
    int h  = blockIdx.y, b = blockIdx.z;
    int tid = threadIdx.x;
    int tx = tid & 15, ty = tid >> 4;

    const float* qb = qkv + (size_t)b * SEQ * D3 + h * 64;
    const float* kb = qb + 1024;
    const float* vb = qb + 2048;

    #pragma unroll
    for (int u = 0; u < 4; u++) {
        int idx = tid + u * 256;
        int r = idx >> 4, eq = idx & 15;
        float4 a = *(const float4*)(qb + (size_t)(q0 + r) * D3 + eq * 4);
        Qt[(eq * 4 + 0) * 64 + r] = a.x * 0.125f;
        Qt[(eq * 4 + 1) * 64 + r] = a.y * 0.125f;
        Qt[(eq * 4 + 2) * 64 + r] = a.z * 0.125f;
        Qt[(eq * 4 + 3) * 64 + r] = a.w * 0.125f;
    }

    float m_i[4], l_i[4], acc[4][4];
    #pragma unroll
    for (int i = 0; i < 4; i++) {
        m_i[i] = -INFINITY; l_i[i] = 0.f;
        #pragma unroll
        for (int j = 0; j < 4; j++) acc[i][j] = 0.f;
    }

    int ntiles = (q0 >> 6) + 1;
    for (int t = 0; t < ntiles; t++) {
        int j0 = t << 6;
        __syncthreads();   // previous P·V done before overwriting KP/Vs
        #pragma unroll
        for (int u = 0; u < 4; u++) {
            int idx = tid + u * 256;
            int r = idx >> 4, eq = idx & 15;
            float4 a = *(const float4*)(kb + (size_t)(j0 + r) * D3 + eq * 4);
            KP[(eq * 4 + 0) * 64 + r] = a.x;
            KP[(eq * 4 + 1) * 64 + r] = a.y;
            KP[(eq * 4 + 2) * 64 + r] = a.z;
            KP[(eq * 4 + 3) * 64 + r] = a.w;
            float4 v = *(const float4*)(vb + (size_t)(j0 + r) * D3 + eq * 4);
            *(float4*)&Vs[r * 64 + eq * 4] = v;
        }
        __syncthreads();

        // S = (Q/8) K^T  (64x64, 4x4 per thread)
        float s[4][4];
        #pragma unroll
        for (int i = 0; i < 4; i++)
            #pragma unroll
            for (int j = 0; j < 4; j++) s[i][j] = 0.f;
        #pragma unroll 8
        for (int e = 0; e < 64; e++) {
            float4 qa = *(const float4*)&Qt[e * 64 + ty * 4];
            float4 ka = *(const float4*)&KP[e * 64 + tx * 4];
            float qr[4] = {qa.x, qa.y, qa.z, qa.w};
            float kr[4] = {ka.x, ka.y, ka.z, ka.w};
            #pragma unroll
            for (int i = 0; i < 4; i++)
                #pragma unroll
                for (int j = 0; j < 4; j++)
                    s[i][j] = fmaf(qr[i], kr[j], s[i][j]);
        }

        if (j0 == q0) {  // only diagonal tile needs masking
            #pragma unroll
            for (int i = 0; i < 4; i++)
                #pragma unroll
                for (int j = 0; j < 4; j++)
                    if (j0 + tx * 4 + j > q0 + ty * 4 + i) s[i][j] = -1e30f;
        }

        // row max across 16 tx-lanes
        float mt[4];
        #pragma unroll
        for (int i = 0; i < 4; i++)
            mt[i] = fmaxf(fmaxf(s[i][0], s[i][1]), fmaxf(s[i][2], s[i][3]));
        #pragma unroll
        for (int o = 8; o > 0; o >>= 1)
            #pragma unroll
            for (int i = 0; i < 4; i++)
                mt[i] = fmaxf(mt[i], __shfl_xor_sync(0xffffffffu, mt[i], o, 16));

        float rs[4];
        #pragma unroll
        for (int i = 0; i < 4; i++) {
            float mn = fmaxf(m_i[i], mt[i]);
            float al = __expf(m_i[i] - mn);
            m_i[i] = mn;
            float r = 0.f;
            #pragma unroll
            for (int j = 0; j < 4; j++) {
                s[i][j] = __expf(s[i][j] - mn);
                r += s[i][j];
            }
            rs[i] = r;
            l_i[i] *= al;
            #pragma unroll
            for (int j = 0; j < 4; j++) acc[i][j] *= al;
        }
        #pragma unroll
        for (int o = 8; o > 0; o >>= 1)
            #pragma unroll
            for (int i = 0; i < 4; i++)
                rs[i] += __shfl_xor_sync(0xffffffffu, rs[i], o, 16);
        #pragma unroll
        for (int i = 0; i < 4; i++) l_i[i] += rs[i];

        __syncthreads();   // everyone done reading KP as K before P overwrite
        #pragma unroll
        for (int i = 0; i < 4; i++)
            *(float4*)&KP[(ty * 4 + i) * 64 + tx * 4] =
                make_float4(s[i][0], s[i][1], s[i][2], s[i][3]);
        __syncthreads();

        // acc += P @ V
        #pragma unroll 8
        for (int k = 0; k < 64; k++) {
            float pa[4];
            #pragma unroll
            for (int i = 0; i < 4; i++) pa[i] = KP[(ty * 4 + i) * 64 + k];
            float4 va = *(const float4*)&Vs[k * 64 + tx * 4];
            float vr[4] = {va.x, va.y, va.z, va.w};
            #pragma unroll
            for (int i = 0; i < 4; i++)
                #pragma unroll
                for (int j = 0; j < 4; j++)
                    acc[i][j] = fmaf(pa[i], vr[j], acc[i][j]);
        }
    }

    #pragma unroll
    for (int i = 0; i < 4; i++) {
        float inv = 1.f / l_i[i];
        size_t row = (size_t)b * SEQ + q0 + ty * 4 + i;
        float4 o = make_float4(acc[i][0] * inv, acc[i][1] * inv,
                               acc[i][2] * inv, acc[i][3] * inv);
        *(float4*)&z[row * DRES + h * 64 + tx * 4] = o;
    }
}

// ---------------- launch ------------------------------------------------------
extern "C" void kernel_launch(void* const* d_in, const int* in_sizes, int n_in,
                              void* d_out, int out_size)
{
    const float* resid_pre = (const float*)d_in[0];
    const float* ln1_w     = (const float*)d_in[1];
    const float* ln1_b     = (const float*)d_in[2];
    const float* WQ        = (const float*)d_in[3];
    const float* bQ        = (const float*)d_in[4];
    const float* WK        = (const float*)d_in[5];
    const float* bK        = (const float*)d_in[6];
    const float* WV        = (const float*)d_in[7];
    const float* bV        = (const float*)d_in[8];
    const float* WO        = (const float*)d_in[9];
    const float* bO        = (const float*)d_in[10];
    const float* ln2_w     = (const float*)d_in[11];
    const float* ln2_b     = (const float*)d_in[12];
    const float* Win       = (const float*)d_in[13];
    const float* bin       = (const float*)d_in[14];
    const float* Wout      = (const float*)d_in[15];
    const float* bout      = (const float*)d_in[16];
    float* out = (float*)d_out;

    float *x, *qkv, *Wqkv, *bqkv, *z, *rm, *mlp;
    cudaGetSymbolAddress((void**)&x,    g_x);
    cudaGetSymbolAddress((void**)&qkv,  g_qkv);
    cudaGetSymbolAddress((void**)&Wqkv, g_Wqkv);
    cudaGetSymbolAddress((void**)&bqkv, g_bqkv);
    cudaGetSymbolAddress((void**)&z,    g_z);
    cudaGetSymbolAddress((void**)&rm,   g_rm);
    cudaGetSymbolAddress((void**)&mlp,  g_mlp);

    // repack QKV weights -> [1024, 3072]
    repack_kernel<<<(DRES * D3) / 256, 256>>>(WQ, WK, WV, bQ, bK, bV);

    // LN1
    ln_kernel<<<T_TOK, 256>>>(resid_pre, ln1_w, ln1_b, x);

    // QKV projection: [4096,1024] @ [1024,3072]
    sgemm_kernel<<<dim3(D3 / 128, T_TOK / 128), 256>>>(
        x, Wqkv, bqkv, nullptr, qkv, T_TOK, D3, DRES, 0);

    // causal flash attention
    attn_kernel<<<dim3(SEQ / 64, NH, 2), 256>>>(qkv, z);

    // O projection + residual: resid_mid = resid_pre + z @ W_O + b_O
    sgemm_kernel<<<dim3(DRES / 128, T_TOK / 128), 256>>>(
        z, WO, bO, resid_pre, rm, T_TOK, DRES, DRES, 1);

    // LN2
    ln_kernel<<<T_TOK, 256>>>(rm, ln2_w, ln2_b, x);

    // MLP in + exact GELU: [4096,1024] @ [1024,4096]
    sgemm_kernel<<<dim3(DMLP / 128, T_TOK / 128), 256>>>(
        x, Win, bin, nullptr, mlp, T_TOK, DMLP, DRES, 2);

    // MLP out + residual -> final output
    sgemm_kernel<<<dim3(DRES / 128, T_TOK / 128), 256>>>(
        mlp, Wout, bout, rm, out, T_TOK, DRES, DMLP, 1);
}

// round 5
// speedup vs baseline: 2.5097x; 2.5097x over previous
#include <cuda_runtime.h>
#include <math.h>

#define T_TOK 4096
#define SEQ   2048
#define DRES  1024
#define D3    3072
#define DMLP  4096
#define NH    16

// ---------------- device scratch (allocation-free rule: __device__ globals) ----
__device__ float g_x[(size_t)T_TOK * DRES];        // ln output (reused for ln1 & ln2)
__device__ float g_qkv[(size_t)T_TOK * D3];        // [t, 3072]: Q | K | V, head-major
__device__ float g_Wqkv[(size_t)DRES * D3];        // repacked [K=1024, N=3072]
__device__ float g_bqkv[D3];
__device__ float g_z[(size_t)T_TOK * DRES];        // attention out [t, h*64+e]
__device__ float g_rm[(size_t)T_TOK * DRES];       // resid_mid
__device__ float g_mlp[(size_t)T_TOK * DMLP];      // mlp hidden (post-gelu)

// ---------------- repack QKV weights into one [1024,3072] row-major B ---------
__global__ __launch_bounds__(256) void repack_kernel(
    const float* __restrict__ WQ, const float* __restrict__ WK,
    const float* __restrict__ WV, const float* __restrict__ bQ,
    const float* __restrict__ bK, const float* __restrict__ bV)
{
    int idx = blockIdx.x * 256 + threadIdx.x;
    if (idx < D3) {
        g_bqkv[idx] = (idx < 1024) ? bQ[idx]
                    : (idx < 2048) ? bK[idx - 1024]
                    :                bV[idx - 2048];
    }
    if (idx >= DRES * D3) return;
    int d = idx / D3;
    int j = idx % D3;
    const float* W = WQ; int jj = j;
    if (j >= 2048)      { W = WV; jj = j - 2048; }
    else if (j >= 1024) { W = WK; jj = j - 1024; }
    g_Wqkv[idx] = W[((jj >> 6) << 16) + (d << 6) + (jj & 63)];
}

// ---------------- layernorm: one block per row of 1024 ------------------------
__global__ __launch_bounds__(256) void ln_kernel(
    const float* __restrict__ x, const float* __restrict__ w,
    const float* __restrict__ b, float* __restrict__ y)
{
    __shared__ float red[8];
    __shared__ float sMean, sRstd;
    int row = blockIdx.x, tid = threadIdx.x;
    const float* xr = x + (size_t)row * DRES;
    float4 v = ((const float4*)xr)[tid];

    float s = v.x + v.y + v.z + v.w;
    #pragma unroll
    for (int o = 16; o > 0; o >>= 1) s += __shfl_xor_sync(0xffffffffu, s, o);
    if ((tid & 31) == 0) red[tid >> 5] = s;
    __syncthreads();
    if (tid == 0) {
        float t = 0.f;
        #pragma unroll
        for (int i = 0; i < 8; i++) t += red[i];
        sMean = t * (1.f / DRES);
    }
    __syncthreads();
    float mean = sMean;
    float cx = v.x - mean, cy = v.y - mean, cz = v.z - mean, cw = v.w - mean;
    float sq = cx * cx + cy * cy + cz * cz + cw * cw;
    #pragma unroll
    for (int o = 16; o > 0; o >>= 1) sq += __shfl_xor_sync(0xffffffffu, sq, o);
    if ((tid & 31) == 0) red[tid >> 5] = sq;
    __syncthreads();
    if (tid == 0) {
        float t = 0.f;
        #pragma unroll
        for (int i = 0; i < 8; i++) t += red[i];
        sRstd = rsqrtf(t * (1.f / DRES) + 1e-5f);
    }
    __syncthreads();
    float rstd = sRstd;
    float4 wv = ((const float4*)w)[tid];
    float4 bv = ((const float4*)b)[tid];
    float4 o;
    o.x = cx * rstd * wv.x + bv.x;
    o.y = cy * rstd * wv.y + bv.y;
    o.z = cz * rstd * wv.z + bv.z;
    o.w = cw * rstd * wv.w + bv.w;
    ((float4*)(y + (size_t)row * DRES))[tid] = o;
}

// ---------------- TF32 tensor-core GEMM ---------------------------------------
// C[M,N] = A[M,K] @ B[K,N] + bias[N]  (+residual | gelu)
// 128x128 block tile, K-tile 32, 8 warps (2m x 4n), 64x32 warp tile,
// mma.sync.m16n8k8 tf32, 2-stage cp.async pipeline.
__device__ __forceinline__ float gelu_exact(float x) {
    return 0.5f * x * (1.0f + erff(x * 0.70710678118654752f));
}

#define AS_STRIDE 36
#define STAGE_FLOATS (128 * AS_STRIDE + 32 * 128)   // 4608 + 4096 = 8704
#define SMEM_BYTES (2 * STAGE_FLOATS * 4)           // 69632

__device__ __forceinline__ void cp_async16(void* smem_dst, const void* gmem_src) {
    unsigned saddr = (unsigned)__cvta_generic_to_shared(smem_dst);
    asm volatile("cp.async.cg.shared.global [%0], [%1], 16;\n"
                 :: "r"(saddr), "l"(gmem_src));
}

__device__ __forceinline__ void load_stage(
    float* As, float* Bs,
    const float* __restrict__ A, const float* __restrict__ B,
    int m0, int n0, int kt, int K, int N, int tid)
{
    // A tile: 128m x 32k. linear -> m = lin>>3, kq = lin&7 (float4 along k).
    #pragma unroll
    for (int u = 0; u < 4; u++) {
        int lin = u * 256 + tid;
        int m = lin >> 3, kq = lin & 7;
        cp_async16(As + m * AS_STRIDE + kq * 4,
                   A + (size_t)(m0 + m) * K + kt + kq * 4);
    }
    // B tile: 32k x 128n, xor swizzle n ^ ((k&7)<<3)
    #pragma unroll
    for (int u = 0; u < 4; u++) {
        int lin = u * 256 + tid;
        int kr = lin >> 5, nc = (lin & 31) * 4;
        int swz = nc ^ ((kr & 7) << 3);
        cp_async16(Bs + kr * 128 + swz,
                   B + (size_t)(kt + kr) * N + n0 + nc);
    }
}

__global__ __launch_bounds__(256, 2) void sgemm_tc_kernel(
    const float* __restrict__ A, const float* __restrict__ B,
    const float* __restrict__ bias, const float* __restrict__ res,
    float* __restrict__ C, int M, int N, int K, int mode)
{
    extern __shared__ float smem[];
    int tid = threadIdx.x;
    int lane = tid & 31;
    int warp = tid >> 5;
    int warp_m = warp & 1;        // 0..1
    int warp_n = warp >> 1;       // 0..3
    int m0 = blockIdx.y * 128, n0 = blockIdx.x * 128;

    float c[4][4][4];   // [mt][nt][frag]
    #pragma unroll
    for (int i = 0; i < 4; i++)
        #pragma unroll
        for (int j = 0; j < 4; j++)
            #pragma unroll
            for (int f = 0; f < 4; f++) c[i][j][f] = 0.f;

    int KT = K >> 5;

    // prologue: stage 0
    load_stage(smem, smem + 128 * AS_STRIDE, A, B, m0, n0, 0, K, N, tid);
    asm volatile("cp.async.commit_group;\n");

    for (int t = 0; t < KT; t++) {
        int nbuf = (t + 1) & 1;
        if (t + 1 < KT) {
            float* Asn = smem + nbuf * STAGE_FLOATS;
            load_stage(Asn, Asn + 128 * AS_STRIDE, A, B, m0, n0, (t + 1) * 32, K, N, tid);
        }
        asm volatile("cp.async.commit_group;\n");
        asm volatile("cp.async.wait_group 1;\n");
        __syncthreads();

        const float* As = smem + (t & 1) * STAGE_FLOATS;
        const float* Bs = As + 128 * AS_STRIDE;

        #pragma unroll
        for (int ks = 0; ks < 4; ks++) {
            int kb = ks * 8;
            // load A fragments: 4 mtiles
            unsigned a[4][4];
            #pragma unroll
            for (int mt = 0; mt < 4; mt++) {
                int row = warp_m * 64 + mt * 16 + (lane >> 2);
                int col = kb + (lane & 3);
                a[mt][0] = *(const unsigned*)&As[row * AS_STRIDE + col];
                a[mt][1] = *(const unsigned*)&As[(row + 8) * AS_STRIDE + col];
                a[mt][2] = *(const unsigned*)&As[row * AS_STRIDE + col + 4];
                a[mt][3] = *(const unsigned*)&As[(row + 8) * AS_STRIDE + col + 4];
            }
            // load B fragments: 4 ntiles
            unsigned bfr[4][2];
            #pragma unroll
            for (int nt = 0; nt < 4; nt++) {
                int n = warp_n * 32 + nt * 8 + (lane >> 2);
                int k0 = kb + (lane & 3);
                int k1 = k0 + 4;
                bfr[nt][0] = *(const unsigned*)&Bs[k0 * 128 + (n ^ ((k0 & 7) << 3))];
                bfr[nt][1] = *(const unsigned*)&Bs[k1 * 128 + (n ^ ((k1 & 7) << 3))];
            }
            #pragma unroll
            for (int mt = 0; mt < 4; mt++)
                #pragma unroll
                for (int nt = 0; nt < 4; nt++) {
                    asm volatile(
                        "mma.sync.aligned.m16n8k8.row.col.f32.tf32.tf32.f32 "
                        "{%0,%1,%2,%3}, {%4,%5,%6,%7}, {%8,%9}, {%0,%1,%2,%3};\n"
                        : "+f"(c[mt][nt][0]), "+f"(c[mt][nt][1]),
                          "+f"(c[mt][nt][2]), "+f"(c[mt][nt][3])
                        : "r"(a[mt][0]), "r"(a[mt][1]), "r"(a[mt][2]), "r"(a[mt][3]),
                          "r"(bfr[nt][0]), "r"(bfr[nt][1]));
                }
        }
        __syncthreads();
    }

    // epilogue
    #pragma unroll
    for (int mt = 0; mt < 4; mt++) {
        int r0 = m0 + warp_m * 64 + mt * 16 + (lane >> 2);
        #pragma unroll
        for (int nt = 0; nt < 4; nt++) {
            int col = n0 + warp_n * 32 + nt * 8 + 2 * (lane & 3);
            float2 bb = *(const float2*)(bias + col);
            float2 v0 = make_float2(c[mt][nt][0] + bb.x, c[mt][nt][1] + bb.y);
            float2 v1 = make_float2(c[mt][nt][2] + bb.x, c[mt][nt][3] + bb.y);
            if (mode == 1) {
                float2 ra = *(const float2*)(res + (size_t)r0 * N + col);
                float2 rb = *(const float2*)(res + (size_t)(r0 + 8) * N + col);
                v0.x += ra.x; v0.y += ra.y;
                v1.x += rb.x; v1.y += rb.y;
            } else if (mode == 2) {
                v0.x = gelu_exact(v0.x); v0.y = gelu_exact(v0.y);
                v1.x = gelu_exact(v1.x); v1.y = gelu_exact(v1.y);
            }
            *(float2*)(C + (size_t)r0 * N + col) = v0;
            *(float2*)(C + (size_t)(r0 + 8) * N + col) = v1;
        }
    }
}

// ---------------- flash attention: 64-query tile, online softmax --------------
__global__ __launch_bounds__(256) void attn_kernel(
    const float* __restrict__ qkv, float* __restrict__ z)
{
    __shared__ float Qt[64 * 64];
    __shared__ float KP[64 * 64];
    __shared__ float Vs[64 * 64];
    int q0 = blockIdx.x << 6;
    int h  = blockIdx.y, b = blockIdx.z;
    int tid = threadIdx.x;
    int tx = tid & 15, ty = tid >> 4;

    const float* qb = qkv + (size_t)b * SEQ * D3 + h * 64;
    const float* kb = qb + 1024;
    const float* vb = qb + 2048;

    #pragma unroll
    for (int u = 0; u < 4; u++) {
        int idx = tid + u * 256;
        int r = idx >> 4, eq = idx & 15;
        float4 a = *(const float4*)(qb + (size_t)(q0 + r) * D3 + eq * 4);
        Qt[(eq * 4 + 0) * 64 + r] = a.x * 0.125f;
        Qt[(eq * 4 + 1) * 64 + r] = a.y * 0.125f;
        Qt[(eq * 4 + 2) * 64 + r] = a.z * 0.125f;
        Qt[(eq * 4 + 3) * 64 + r] = a.w * 0.125f;
    }

    float m_i[4], l_i[4], acc[4][4];
    #pragma unroll
    for (int i = 0; i < 4; i++) {
        m_i[i] = -INFINITY; l_i[i] = 0.f;
        #pragma unroll
        for (int j = 0; j < 4; j++) acc[i][j] = 0.f;
    }

    int ntiles = (q0 >> 6) + 1;
    for (int t = 0; t < ntiles; t++) {
        int j0 = t << 6;
        __syncthreads();
        #pragma unroll
        for (int u = 0; u < 4; u++) {
            int idx = tid + u * 256;
            int r = idx >> 4, eq = idx & 15;
            float4 a = *(const float4*)(kb + (size_t)(j0 + r) * D3 + eq * 4);
            KP[(eq * 4 + 0) * 64 + r] = a.x;
            KP[(eq * 4 + 1) * 64 + r] = a.y;
            KP[(eq * 4 + 2) * 64 + r] = a.z;
            KP[(eq * 4 + 3) * 64 + r] = a.w;
            float4 v = *(const float4*)(vb + (size_t)(j0 + r) * D3 + eq * 4);
            *(float4*)&Vs[r * 64 + eq * 4] = v;
        }
        __syncthreads();

        float s[4][4];
        #pragma unroll
        for (int i = 0; i < 4; i++)
            #pragma unroll
            for (int j = 0; j < 4; j++) s[i][j] = 0.f;
        #pragma unroll 8
        for (int e = 0; e < 64; e++) {
            float4 qa = *(const float4*)&Qt[e * 64 + ty * 4];
            float4 ka = *(const float4*)&KP[e * 64 + tx * 4];
            float qr[4] = {qa.x, qa.y, qa.z, qa.w};
            float kr[4] = {ka.x, ka.y, ka.z, ka.w};
            #pragma unroll
            for (int i = 0; i < 4; i++)
                #pragma unroll
                for (int j = 0; j < 4; j++)
                    s[i][j] = fmaf(qr[i], kr[j], s[i][j]);
        }

        if (j0 == q0) {
            #pragma unroll
            for (int i = 0; i < 4; i++)
                #pragma unroll
                for (int j = 0; j < 4; j++)
                    if (j0 + tx * 4 + j > q0 + ty * 4 + i) s[i][j] = -1e30f;
        }

        float mt[4];
        #pragma unroll
        for (int i = 0; i < 4; i++)
            mt[i] = fmaxf(fmaxf(s[i][0], s[i][1]), fmaxf(s[i][2], s[i][3]));
        #pragma unroll
        for (int o = 8; o > 0; o >>= 1)
            #pragma unroll
            for (int i = 0; i < 4; i++)
                mt[i] = fmaxf(mt[i], __shfl_xor_sync(0xffffffffu, mt[i], o, 16));

        float rs[4];
        #pragma unroll
        for (int i = 0; i < 4; i++) {
            float mn = fmaxf(m_i[i], mt[i]);
            float al = __expf(m_i[i] - mn);
            m_i[i] = mn;
            float r = 0.f;
            #pragma unroll
            for (int j = 0; j < 4; j++) {
                s[i][j] = __expf(s[i][j] - mn);
                r += s[i][j];
            }
            rs[i] = r;
            l_i[i] *= al;
            #pragma unroll
            for (int j = 0; j < 4; j++) acc[i][j] *= al;
        }
        #pragma unroll
        for (int o = 8; o > 0; o >>= 1)
            #pragma unroll
            for (int i = 0; i < 4; i++)
                rs[i] += __shfl_xor_sync(0xffffffffu, rs[i], o, 16);
        #pragma unroll
        for (int i = 0; i < 4; i++) l_i[i] += rs[i];

        __syncthreads();
        #pragma unroll
        for (int i = 0; i < 4; i++)
            *(float4*)&KP[(ty * 4 + i) * 64 + tx * 4] =
                make_float4(s[i][0], s[i][1], s[i][2], s[i][3]);
        __syncthreads();

        #pragma unroll 8
        for (int k = 0; k < 64; k++) {
            float pa[4];
            #pragma unroll
            for (int i = 0; i < 4; i++) pa[i] = KP[(ty * 4 + i) * 64 + k];
            float4 va = *(const float4*)&Vs[k * 64 + tx * 4];
            float vr[4] = {va.x, va.y, va.z, va.w};
            #pragma unroll
            for (int i = 0; i < 4; i++)
                #pragma unroll
                for (int j = 0; j < 4; j++)
                    acc[i][j] = fmaf(pa[i], vr[j], acc[i][j]);
        }
    }

    #pragma unroll
    for (int i = 0; i < 4; i++) {
        float inv = 1.f / l_i[i];
        size_t row = (size_t)b * SEQ + q0 + ty * 4 + i;
        float4 o = make_float4(acc[i][0] * inv, acc[i][1] * inv,
                               acc[i][2] * inv, acc[i][3] * inv);
        *(float4*)&z[row * DRES + h * 64 + tx * 4] = o;
    }
}

// ---------------- launch ------------------------------------------------------
extern "C" void kernel_launch(void* const* d_in, const int* in_sizes, int n_in,
                              void* d_out, int out_size)
{
    const float* resid_pre = (const float*)d_in[0];
    const float* ln1_w     = (const float*)d_in[1];
    const float* ln1_b     = (const float*)d_in[2];
    const float* WQ        = (const float*)d_in[3];
    const float* bQ        = (const float*)d_in[4];
    const float* WK        = (const float*)d_in[5];
    const float* bK        = (const float*)d_in[6];
    const float* WV        = (const float*)d_in[7];
    const float* bV        = (const float*)d_in[8];
    const float* WO        = (const float*)d_in[9];
    const float* bO        = (const float*)d_in[10];
    const float* ln2_w     = (const float*)d_in[11];
    const float* ln2_b     = (const float*)d_in[12];
    const float* Win       = (const float*)d_in[13];
    const float* bin       = (const float*)d_in[14];
    const float* Wout      = (const float*)d_in[15];
    const float* bout      = (const float*)d_in[16];
    float* out = (float*)d_out;

    float *x, *qkv, *Wqkv, *bqkv, *z, *rm, *mlp;
    cudaGetSymbolAddress((void**)&x,    g_x);
    cudaGetSymbolAddress((void**)&qkv,  g_qkv);
    cudaGetSymbolAddress((void**)&Wqkv, g_Wqkv);
    cudaGetSymbolAddress((void**)&bqkv, g_bqkv);
    cudaGetSymbolAddress((void**)&z,    g_z);
    cudaGetSymbolAddress((void**)&rm,   g_rm);
    cudaGetSymbolAddress((void**)&mlp,  g_mlp);

    cudaFuncSetAttribute(sgemm_tc_kernel,
                         cudaFuncAttributeMaxDynamicSharedMemorySize, SMEM_BYTES);

    // repack QKV weights -> [1024, 3072]
    repack_kernel<<<(DRES * D3) / 256, 256>>>(WQ, WK, WV, bQ, bK, bV);

    // LN1
    ln_kernel<<<T_TOK, 256>>>(resid_pre, ln1_w, ln1_b, x);

    // QKV projection: [4096,1024] @ [1024,3072]
    sgemm_tc_kernel<<<dim3(D3 / 128, T_TOK / 128), 256, SMEM_BYTES>>>(
        x, Wqkv, bqkv, nullptr, qkv, T_TOK, D3, DRES, 0);

    // causal flash attention
    attn_kernel<<<dim3(SEQ / 64, NH, 2), 256>>>(qkv, z);

    // O projection + residual
    sgemm_tc_kernel<<<dim3(DRES / 128, T_TOK / 128), 256, SMEM_BYTES>>>(
        z, WO, bO, resid_pre, rm, T_TOK, DRES, DRES, 1);

    // LN2
    ln_kernel<<<T_TOK, 256>>>(rm, ln2_w, ln2_b, x);

    // MLP in + exact GELU
    sgemm_tc_kernel<<<dim3(DMLP / 128, T_TOK / 128), 256, SMEM_BYTES>>>(
        x, Win, bin, nullptr, mlp, T_TOK, DMLP, DRES, 2);

    // MLP out + residual -> final output
    sgemm_tc_kernel<<<dim3(DRES / 128, T_TOK / 128), 256, SMEM_BYTES>>>(
        mlp, Wout, bout, rm, out, T_TOK, DRES, DMLP, 1);
}

// round 7
// speedup vs baseline: 4.0158x; 1.6001x over previous
#include <cuda_runtime.h>
#include <cuda_fp16.h>
#include <math.h>

#define T_TOK 4096
#define SEQ   2048
#define DRES  1024
#define D3    3072
#define DMLP  4096
#define NH    16

// ---------------- device scratch ----------------------------------------------
__device__ float g_x[(size_t)T_TOK * DRES];
__device__ float g_qkv[(size_t)T_TOK * D3];
__device__ float g_Wqkv[(size_t)DRES * D3];
__device__ float g_bqkv[D3];
__device__ float g_z[(size_t)T_TOK * DRES];
__device__ float g_rm[(size_t)T_TOK * DRES];
__device__ float g_mlp[(size_t)T_TOK * DMLP];
__device__ float g_WO[(size_t)DRES * DRES];
__device__ float g_Win[(size_t)DRES * DMLP];
__device__ float g_Wout[(size_t)DMLP * DRES];

// ---------------- tf32 round-to-nearest helpers -------------------------------
__device__ __forceinline__ unsigned rna_u(float x) {
    unsigned u;
    asm("cvt.rna.tf32.f32 %0, %1;\n" : "=r"(u) : "f"(x));
    return u;
}
__device__ __forceinline__ float rna_f(float x) {
    return __uint_as_float(rna_u(x));
}

// ---------------- weight rounding pass ----------------------------------------
__global__ __launch_bounds__(256) void round_kernel(
    const float* __restrict__ src, float* __restrict__ dst, int n4)
{
    int i = blockIdx.x * 256 + threadIdx.x;
    if (i >= n4) return;
    float4 v = ((const float4*)src)[i];
    v.x = rna_f(v.x); v.y = rna_f(v.y); v.z = rna_f(v.z); v.w = rna_f(v.w);
    ((float4*)dst)[i] = v;
}

// ---------------- repack QKV weights into one [1024,3072] row-major B ---------
__global__ __launch_bounds__(256) void repack_kernel(
    const float* __restrict__ WQ, const float* __restrict__ WK,
    const float* __restrict__ WV, const float* __restrict__ bQ,
    const float* __restrict__ bK, const float* __restrict__ bV)
{
    int idx = blockIdx.x * 256 + threadIdx.x;
    if (idx < D3) {
        g_bqkv[idx] = (idx < 1024) ? bQ[idx]
                    : (idx < 2048) ? bK[idx - 1024]
                    :                bV[idx - 2048];
    }
    if (idx >= DRES * D3) return;
    int d = idx / D3;
    int j = idx % D3;
    const float* W = WQ; int jj = j;
    if (j >= 2048)      { W = WV; jj = j - 2048; }
    else if (j >= 1024) { W = WK; jj = j - 1024; }
    g_Wqkv[idx] = rna_f(W[((jj >> 6) << 16) + (d << 6) + (jj & 63)]);
}

// ---------------- layernorm (output rounded to tf32: feeds GEMM A) ------------
__global__ __launch_bounds__(256) void ln_kernel(
    const float* __restrict__ x, const float* __restrict__ w,
    const float* __restrict__ b, float* __restrict__ y)
{
    __shared__ float red[8];
    __shared__ float sMean, sRstd;
    int row = blockIdx.x, tid = threadIdx.x;
    const float* xr = x + (size_t)row * DRES;
    float4 v = ((const float4*)xr)[tid];

    float s = v.x + v.y + v.z + v.w;
    #pragma unroll
    for (int o = 16; o > 0; o >>= 1) s += __shfl_xor_sync(0xffffffffu, s, o);
    if ((tid & 31) == 0) red[tid >> 5] = s;
    __syncthreads();
    if (tid == 0) {
        float t = 0.f;
        #pragma unroll
        for (int i = 0; i < 8; i++) t += red[i];
        sMean = t * (1.f / DRES);
    }
    __syncthreads();
    float mean = sMean;
    float cx = v.x - mean, cy = v.y - mean, cz = v.z - mean, cw = v.w - mean;
    float sq = cx * cx + cy * cy + cz * cz + cw * cw;
    #pragma unroll
    for (int o = 16; o > 0; o >>= 1) sq += __shfl_xor_sync(0xffffffffu, sq, o);
    if ((tid & 31) == 0) red[tid >> 5] = sq;
    __syncthreads();
    if (tid == 0) {
        float t = 0.f;
        #pragma unroll
        for (int i = 0; i < 8; i++) t += red[i];
        sRstd = rsqrtf(t * (1.f / DRES) + 1e-5f);
    }
    __syncthreads();
    float rstd = sRstd;
    float4 wv = ((const float4*)w)[tid];
    float4 bv = ((const float4*)b)[tid];
    float4 o;
    o.x = rna_f(cx * rstd * wv.x + bv.x);
    o.y = rna_f(cy * rstd * wv.y + bv.y);
    o.z = rna_f(cz * rstd * wv.z + bv.z);
    o.w = rna_f(cw * rstd * wv.w + bv.w);
    ((float4*)(y + (size_t)row * DRES))[tid] = o;
}

// ---------------- TF32 tensor-core GEMM ---------------------------------------
__device__ __forceinline__ float gelu_exact(float x) {
    return 0.5f * x * (1.0f + erff(x * 0.70710678118654752f));
}

#define AS_STRIDE 36
#define STAGE_FLOATS (128 * AS_STRIDE + 32 * 128)
#define SMEM_BYTES (2 * STAGE_FLOATS * 4)

__device__ __forceinline__ void cp_async16(void* smem_dst, const void* gmem_src) {
    unsigned saddr = (unsigned)__cvta_generic_to_shared(smem_dst);
    asm volatile("cp.async.cg.shared.global [%0], [%1], 16;\n"
                 :: "r"(saddr), "l"(gmem_src));
}

__device__ __forceinline__ void load_stage(
    float* As, float* Bs,
    const float* __restrict__ A, const float* __restrict__ B,
    int m0, int n0, int kt, int K, int N, int tid)
{
    #pragma unroll
    for (int u = 0; u < 4; u++) {
        int lin = u * 256 + tid;
        int m = lin >> 3, kq = lin & 7;
        cp_async16(As + m * AS_STRIDE + kq * 4,
                   A + (size_t)(m0 + m) * K + kt + kq * 4);
    }
    #pragma unroll
    for (int u = 0; u < 4; u++) {
        int lin = u * 256 + tid;
        int kr = lin >> 5, nc = (lin & 31) * 4;
        int swz = nc ^ ((kr & 7) << 3);
        cp_async16(Bs + kr * 128 + swz,
                   B + (size_t)(kt + kr) * N + n0 + nc);
    }
}

__global__ __launch_bounds__(256, 2) void sgemm_tc_kernel(
    const float* __restrict__ A, const float* __restrict__ B,
    const float* __restrict__ bias, const float* __restrict__ res,
    float* __restrict__ C, int M, int N, int K, int mode)
{
    extern __shared__ float smem[];
    int tid = threadIdx.x;
    int lane = tid & 31;
    int warp = tid >> 5;
    int warp_m = warp & 1;
    int warp_n = warp >> 1;
    int m0 = blockIdx.y * 128, n0 = blockIdx.x * 128;

    float c[4][4][4];
    #pragma unroll
    for (int i = 0; i < 4; i++)
        #pragma unroll
        for (int j = 0; j < 4; j++)
            #pragma unroll
            for (int f = 0; f < 4; f++) c[i][j][f] = 0.f;

    int KT = K >> 5;

    load_stage(smem, smem + 128 * AS_STRIDE, A, B, m0, n0, 0, K, N, tid);
    asm volatile("cp.async.commit_group;\n");

    for (int t = 0; t < KT; t++) {
        int nbuf = (t + 1) & 1;
        if (t + 1 < KT) {
            float* Asn = smem + nbuf * STAGE_FLOATS;
            load_stage(Asn, Asn + 128 * AS_STRIDE, A, B, m0, n0, (t + 1) * 32, K, N, tid);
        }
        asm volatile("cp.async.commit_group;\n");
        asm volatile("cp.async.wait_group 1;\n");
        __syncthreads();

        const float* As = smem + (t & 1) * STAGE_FLOATS;
        const float* Bs = As + 128 * AS_STRIDE;

        #pragma unroll
        for (int ks = 0; ks < 4; ks++) {
            int kb = ks * 8;
            unsigned a[4][4];
            #pragma unroll
            for (int mt = 0; mt < 4; mt++) {
                int row = warp_m * 64 + mt * 16 + (lane >> 2);
                int col = kb + (lane & 3);
                a[mt][0] = *(const unsigned*)&As[row * AS_STRIDE + col];
                a[mt][1] = *(const unsigned*)&As[(row + 8) * AS_STRIDE + col];
                a[mt][2] = *(const unsigned*)&As[row * AS_STRIDE + col + 4];
                a[mt][3] = *(const unsigned*)&As[(row + 8) * AS_STRIDE + col + 4];
            }
            unsigned bfr[4][2];
            #pragma unroll
            for (int nt = 0; nt < 4; nt++) {
                int n = warp_n * 32 + nt * 8 + (lane >> 2);
                int k0 = kb + (lane & 3);
                int k1 = k0 + 4;
                bfr[nt][0] = *(const unsigned*)&Bs[k0 * 128 + (n ^ ((k0 & 7) << 3))];
                bfr[nt][1] = *(const unsigned*)&Bs[k1 * 128 + (n ^ ((k1 & 7) << 3))];
            }
            #pragma unroll
            for (int mt = 0; mt < 4; mt++)
                #pragma unroll
                for (int nt = 0; nt < 4; nt++) {
                    asm volatile(
                        "mma.sync.aligned.m16n8k8.row.col.f32.tf32.tf32.f32 "
                        "{%0,%1,%2,%3}, {%4,%5,%6,%7}, {%8,%9}, {%0,%1,%2,%3};\n"
                        : "+f"(c[mt][nt][0]), "+f"(c[mt][nt][1]),
                          "+f"(c[mt][nt][2]), "+f"(c[mt][nt][3])
                        : "r"(a[mt][0]), "r"(a[mt][1]), "r"(a[mt][2]), "r"(a[mt][3]),
                          "r"(bfr[nt][0]), "r"(bfr[nt][1]));
                }
        }
        __syncthreads();
    }

    #pragma unroll
    for (int mt = 0; mt < 4; mt++) {
        int r0 = m0 + warp_m * 64 + mt * 16 + (lane >> 2);
        #pragma unroll
        for (int nt = 0; nt < 4; nt++) {
            int col = n0 + warp_n * 32 + nt * 8 + 2 * (lane & 3);
            float2 bb = *(const float2*)(bias + col);
            float2 v0 = make_float2(c[mt][nt][0] + bb.x, c[mt][nt][1] + bb.y);
            float2 v1 = make_float2(c[mt][nt][2] + bb.x, c[mt][nt][3] + bb.y);
            if (mode == 1) {
                float2 ra = *(const float2*)(res + (size_t)r0 * N + col);
                float2 rb = *(const float2*)(res + (size_t)(r0 + 8) * N + col);
                v0.x += ra.x; v0.y += ra.y;
                v1.x += rb.x; v1.y += rb.y;
            } else if (mode == 2) {
                v0.x = rna_f(gelu_exact(v0.x)); v0.y = rna_f(gelu_exact(v0.y));
                v1.x = rna_f(gelu_exact(v1.x)); v1.y = rna_f(gelu_exact(v1.y));
            }
            *(float2*)(C + (size_t)r0 * N + col) = v0;
            *(float2*)(C + (size_t)(r0 + 8) * N + col) = v1;
        }
    }
}

// ---------------- tensor-core flash attention ---------------------------------
// Br=128 (8 warps x 16 rows), Bc=64. S via mma.m16n8k8.tf32, P*V via
// mma.m16n8k16.f16 (S accum fragment packs directly into fp16 A fragment).
#define KPITCH 68     // floats per K row  -> conflict-free b-frag LDS
#define VPITCH 36     // u32 words per Vt row (72 halfs) -> conflict-free

__global__ __launch_bounds__(256) void attn_tc_kernel(
    const float* __restrict__ qkv, float* __restrict__ z)
{
    __shared__ float    Ks[64 * KPITCH];   // [key][dim] fp32 (tf32-rounded)
    __shared__ unsigned Vt[64 * VPITCH];   // [dim][keypair] half2

    int q0 = blockIdx.x * 128;
    int h  = blockIdx.y, b = blockIdx.z;
    int tid = threadIdx.x, lane = tid & 31, w = tid >> 5;

    const float* qb = qkv + (size_t)b * SEQ * D3 + h * 64;
    const float* kb = qb + 1024;
    const float* vb = qb + 2048;

    int row0 = q0 + w * 16 + (lane >> 2);   // global row for c0/c1 (c2/c3: +8)
    int qcol = lane & 3;

    // Q fragments in registers (tf32 RN, pre-scaled by 1/8)
    unsigned qa[8][4];
    {
        const float* r0p = qb + (size_t)row0 * D3;
        const float* r8p = qb + (size_t)(row0 + 8) * D3;
        #pragma unroll
        for (int k8 = 0; k8 < 8; k8++) {
            int col = k8 * 8 + qcol;
            qa[k8][0] = rna_u(r0p[col] * 0.125f);
            qa[k8][1] = rna_u(r8p[col] * 0.125f);
            qa[k8][2] = rna_u(r0p[col + 4] * 0.125f);
            qa[k8][3] = rna_u(r8p[col + 4] * 0.125f);
        }
    }

    float m0 = -1e30f, m1 = -1e30f, l0 = 0.f, l1 = 0.f;
    float o[8][4];
    #pragma unroll
    for (int nb = 0; nb < 8; nb++) {
        o[nb][0] = 0.f; o[nb][1] = 0.f; o[nb][2] = 0.f; o[nb][3] = 0.f;
    }

    int ntiles = (q0 >> 6) + 2;
    for (int t = 0; t < ntiles; t++) {
        int j0 = t * 64;
        __syncthreads();
        // stage K: 64 keys x 64 dims, tf32-rounded
        #pragma unroll
        for (int it = 0; it < 4; it++) {
            int task = it * 256 + tid;
            int r = task >> 4, c4 = (task & 15) * 4;
            float4 kv = *(const float4*)(kb + (size_t)(j0 + r) * D3 + c4);
            float4 kr;
            kr.x = rna_f(kv.x); kr.y = rna_f(kv.y);
            kr.z = rna_f(kv.z); kr.w = rna_f(kv.w);
            *(float4*)&Ks[r * KPITCH + c4] = kr;
        }
        // stage V transposed: Vt[dim][kp] = half2{V[2kp][dim], V[2kp+1][dim]}
        #pragma unroll
        for (int it = 0; it < 2; it++) {
            int task = it * 256 + tid;
            int eg = task >> 5, kp = task & 31;
            float4 va = *(const float4*)(vb + (size_t)(j0 + 2 * kp) * D3 + eg * 4);
            float4 vc = *(const float4*)(vb + (size_t)(j0 + 2 * kp + 1) * D3 + eg * 4);
            __half2 h0 = __floats2half2_rn(va.x, vc.x);
            __half2 h1 = __floats2half2_rn(va.y, vc.y);
            __half2 h2 = __floats2half2_rn(va.z, vc.z);
            __half2 h3 = __floats2half2_rn(va.w, vc.w);
            Vt[(4 * eg + 0) * VPITCH + kp] = *(unsigned*)&h0;
            Vt[(4 * eg + 1) * VPITCH + kp] = *(unsigned*)&h1;
            Vt[(4 * eg + 2) * VPITCH + kp] = *(unsigned*)&h2;
            Vt[(4 * eg + 3) * VPITCH + kp] = *(unsigned*)&h3;
        }
        __syncthreads();

        // S = (Q/8) K^T : 8 n-blocks x 8 k-steps of mma.m16n8k8.tf32
        float c[8][4];
        #pragma unroll
        for (int nb = 0; nb < 8; nb++) {
            c[nb][0] = 0.f; c[nb][1] = 0.f; c[nb][2] = 0.f; c[nb][3] = 0.f;
            const float* krow = &Ks[(nb * 8 + (lane >> 2)) * KPITCH + (lane & 3)];
            #pragma unroll
            for (int k8 = 0; k8 < 8; k8++) {
                unsigned b0 = *(const unsigned*)&krow[k8 * 8];
                unsigned b1 = *(const unsigned*)&krow[k8 * 8 + 4];
                asm volatile(
                    "mma.sync.aligned.m16n8k8.row.col.f32.tf32.tf32.f32 "
                    "{%0,%1,%2,%3}, {%4,%5,%6,%7}, {%8,%9}, {%0,%1,%2,%3};\n"
                    : "+f"(c[nb][0]), "+f"(c[nb][1]), "+f"(c[nb][2]), "+f"(c[nb][3])
                    : "r"(qa[k8][0]), "r"(qa[k8][1]), "r"(qa[k8][2]), "r"(qa[k8][3]),
                      "r"(b0), "r"(b1));
            }
        }

        // causal mask (only near-diagonal tiles need it)
        if (j0 + 63 > q0 + w * 16) {
            #pragma unroll
            for (int nb = 0; nb < 8; nb++) {
                int key = j0 + nb * 8 + 2 * (lane & 3);
                if (key > row0)         c[nb][0] = -1e30f;
                if (key + 1 > row0)     c[nb][1] = -1e30f;
                if (key > row0 + 8)     c[nb][2] = -1e30f;
                if (key + 1 > row0 + 8) c[nb][3] = -1e30f;
            }
        }

        // online softmax (each row's 64 scores live in a 4-lane quad)
        float mt0 = -1e30f, mt1 = -1e30f;
        #pragma unroll
        for (int nb = 0; nb < 8; nb++) {
            mt0 = fmaxf(mt0, fmaxf(c[nb][0], c[nb][1]));
            mt1 = fmaxf(mt1, fmaxf(c[nb][2], c[nb][3]));
        }
        mt0 = fmaxf(mt0, __shfl_xor_sync(0xffffffffu, mt0, 1));
        mt0 = fmaxf(mt0, __shfl_xor_sync(0xffffffffu, mt0, 2));
        mt1 = fmaxf(mt1, __shfl_xor_sync(0xffffffffu, mt1, 1));
        mt1 = fmaxf(mt1, __shfl_xor_sync(0xffffffffu, mt1, 2));

        float mn0 = fmaxf(m0, mt0), mn1 = fmaxf(m1, mt1);
        float al0 = __expf(m0 - mn0), al1 = __expf(m1 - mn1);
        m0 = mn0; m1 = mn1;

        float rs0 = 0.f, rs1 = 0.f;
        #pragma unroll
        for (int nb = 0; nb < 8; nb++) {
            c[nb][0] = __expf(c[nb][0] - mn0);
            c[nb][1] = __expf(c[nb][1] - mn0);
            c[nb][2] = __expf(c[nb][2] - mn1);
            c[nb][3] = __expf(c[nb][3] - mn1);
            rs0 += c[nb][0] + c[nb][1];
            rs1 += c[nb][2] + c[nb][3];
        }
        rs0 += __shfl_xor_sync(0xffffffffu, rs0, 1);
        rs0 += __shfl_xor_sync(0xffffffffu, rs0, 2);
        rs1 += __shfl_xor_sync(0xffffffffu, rs1, 1);
        rs1 += __shfl_xor_sync(0xffffffffu, rs1, 2);
        l0 = l0 * al0 + rs0;
        l1 = l1 * al1 + rs1;

        #pragma unroll
        for (int nb = 0; nb < 8; nb++) {
            o[nb][0] *= al0; o[nb][1] *= al0;
            o[nb][2] *= al1; o[nb][3] *= al1;
        }

        // pack P into fp16 A-fragments: c-frag cols {2q,2q+1} of n-block 2k+j
        // are exactly a-frag k-halves of k16-block k.
        unsigned pa[4][4];
        #pragma unroll
        for (int kb2 = 0; kb2 < 4; kb2++) {
            __half2 p0 = __floats2half2_rn(c[2 * kb2][0],     c[2 * kb2][1]);
            __half2 p1 = __floats2half2_rn(c[2 * kb2][2],     c[2 * kb2][3]);
            __half2 p2 = __floats2half2_rn(c[2 * kb2 + 1][0], c[2 * kb2 + 1][1]);
            __half2 p3 = __floats2half2_rn(c[2 * kb2 + 1][2], c[2 * kb2 + 1][3]);
            pa[kb2][0] = *(unsigned*)&p0;
            pa[kb2][1] = *(unsigned*)&p1;
            pa[kb2][2] = *(unsigned*)&p2;
            pa[kb2][3] = *(unsigned*)&p3;
        }

        // O += P @ V : 8 n-blocks (output dims) x 4 k16-blocks (keys)
        #pragma unroll
        for (int nb = 0; nb < 8; nb++) {
            const unsigned* vrow = &Vt[(nb * 8 + (lane >> 2)) * VPITCH + (lane & 3)];
            #pragma unroll
            for (int kb2 = 0; kb2 < 4; kb2++) {
                unsigned b0 = vrow[kb2 * 8];
                unsigned b1 = vrow[kb2 * 8 + 4];
                asm volatile(
                    "mma.sync.aligned.m16n8k16.row.col.f32.f16.f16.f32 "
                    "{%0,%1,%2,%3}, {%4,%5,%6,%7}, {%8,%9}, {%0,%1,%2,%3};\n"
                    : "+f"(o[nb][0]), "+f"(o[nb][1]), "+f"(o[nb][2]), "+f"(o[nb][3])
                    : "r"(pa[kb2][0]), "r"(pa[kb2][1]), "r"(pa[kb2][2]), "r"(pa[kb2][3]),
                      "r"(b0), "r"(b1));
            }
        }
    }

    // epilogue: normalize, round to tf32 (feeds O-proj A), store
    float inv0 = 1.f / l0, inv1 = 1.f / l1;
    size_t zr0 = ((size_t)b * SEQ + row0) * DRES + h * 64;
    size_t zr8 = zr0 + (size_t)8 * DRES;
    #pragma unroll
    for (int nb = 0; nb < 8; nb++) {
        int col = nb * 8 + 2 * (lane & 3);
        float2 v0 = make_float2(rna_f(o[nb][0] * inv0), rna_f(o[nb][1] * inv0));
        float2 v1 = make_float2(rna_f(o[nb][2] * inv1), rna_f(o[nb][3] * inv1));
        *(float2*)(z + zr0 + col) = v0;
        *(float2*)(z + zr8 + col) = v1;
    }
}

// ---------------- launch ------------------------------------------------------
extern "C" void kernel_launch(void* const* d_in, const int* in_sizes, int n_in,
                              void* d_out, int out_size)
{
    const float* resid_pre = (const float*)d_in[0];
    const float* ln1_w     = (const float*)d_in[1];
    const float* ln1_b     = (const float*)d_in[2];
    const float* WQ        = (const float*)d_in[3];
    const float* bQ        = (const float*)d_in[4];
    const float* WK        = (const float*)d_in[5];
    const float* bK        = (const float*)d_in[6];
    const float* WV        = (const float*)d_in[7];
    const float* bV        = (const float*)d_in[8];
    const float* WO        = (const float*)d_in[9];
    const float* bO        = (const float*)d_in[10];
    const float* ln2_w     = (const float*)d_in[11];
    const float* ln2_b     = (const float*)d_in[12];
    const float* Win       = (const float*)d_in[13];
    const float* bin       = (const float*)d_in[14];
    const float* Wout      = (const float*)d_in[15];
    const float* bout      = (const float*)d_in[16];
    float* out = (float*)d_out;

    float *x, *qkv, *Wqkv, *bqkv, *z, *rm, *mlp, *rWO, *rWin, *rWout;
    cudaGetSymbolAddress((void**)&x,     g_x);
    cudaGetSymbolAddress((void**)&qkv,   g_qkv);
    cudaGetSymbolAddress((void**)&Wqkv,  g_Wqkv);
    cudaGetSymbolAddress((void**)&bqkv,  g_bqkv);
    cudaGetSymbolAddress((void**)&z,     g_z);
    cudaGetSymbolAddress((void**)&rm,    g_rm);
    cudaGetSymbolAddress((void**)&mlp,   g_mlp);
    cudaGetSymbolAddress((void**)&rWO,   g_WO);
    cudaGetSymbolAddress((void**)&rWin,  g_Win);
    cudaGetSymbolAddress((void**)&rWout, g_Wout);

    cudaFuncSetAttribute(sgemm_tc_kernel,
                         cudaFuncAttributeMaxDynamicSharedMemorySize, SMEM_BYTES);

    // weight prep: repack+round QKV, RN-round remaining weights
    repack_kernel<<<(DRES * D3) / 256, 256>>>(WQ, WK, WV, bQ, bK, bV);
    round_kernel<<<(DRES * DRES / 4) / 256, 256>>>(WO,   rWO,   DRES * DRES / 4);
    round_kernel<<<(DRES * DMLP / 4) / 256, 256>>>(Win,  rWin,  DRES * DMLP / 4);
    round_kernel<<<(DMLP * DRES / 4) / 256, 256>>>(Wout, rWout, DMLP * DRES / 4);

    // LN1 (tf32-rounded output)
    ln_kernel<<<T_TOK, 256>>>(resid_pre, ln1_w, ln1_b, x);

    // QKV projection
    sgemm_tc_kernel<<<dim3(D3 / 128, T_TOK / 128), 256, SMEM_BYTES>>>(
        x, Wqkv, bqkv, nullptr, qkv, T_TOK, D3, DRES, 0);

    // tensor-core causal flash attention
    attn_tc_kernel<<<dim3(SEQ / 128, NH, 2), 256>>>(qkv, z);

    // O projection + residual (residual kept exact fp32)
    sgemm_tc_kernel<<<dim3(DRES / 128, T_TOK / 128), 256, SMEM_BYTES>>>(
        z, rWO, bO, resid_pre, rm, T_TOK, DRES, DRES, 1);

    // LN2 (tf32-rounded output)
    ln_kernel<<<T_TOK, 256>>>(rm, ln2_w, ln2_b, x);

    // MLP in + exact GELU (tf32-rounded output)
    sgemm_tc_kernel<<<dim3(DMLP / 128, T_TOK / 128), 256, SMEM_BYTES>>>(
        x, rWin, bin, nullptr, mlp, T_TOK, DMLP, DRES, 2);

    // MLP out + residual -> final output
    sgemm_tc_kernel<<<dim3(DRES / 128, T_TOK / 128), 256, SMEM_BYTES>>>(
        mlp, rWout, bout, rm, out, T_TOK, DRES, DMLP, 1);
}

// round 8
// speedup vs baseline: 6.4475x; 1.6055x over previous
#include <cuda_runtime.h>
#include <cuda_fp16.h>
#include <math.h>

#define T_TOK 4096
#define SEQ   2048
#define DRES  1024
#define D3    3072
#define DMLP  4096
#define NH    16

// ---------------- device scratch ----------------------------------------------
__device__ __half  g_xh [(size_t)T_TOK * DRES];    // LN output (fp16)
__device__ __half  g_qkvh[(size_t)T_TOK * D3];     // QKV (fp16)
__device__ __half  g_zh [(size_t)T_TOK * DRES];    // attention out (fp16)
__device__ __half  g_mlph[(size_t)T_TOK * DMLP];   // MLP hidden post-gelu (fp16)
__device__ float   g_rm [(size_t)T_TOK * DRES];    // resid_mid (fp32, exact)
__device__ float    g_bqkv[D3];
__device__ unsigned g_Wqkvh[(size_t)(DRES / 2) * D3];   // pair-interleaved half2
__device__ unsigned g_WOh  [(size_t)(DRES / 2) * DRES];
__device__ unsigned g_Winh [(size_t)(DRES / 2) * DMLP];
__device__ unsigned g_Wouth[(size_t)(DMLP / 2) * DRES];

__device__ __forceinline__ unsigned packh2(float a, float b) {
    __half2 h = __floats2half2_rn(a, b);
    return *(unsigned*)&h;
}

// ---------------- weight converts ----------------------------------------------
// Wp[kp][n] = half2{ W[2kp][n], W[2kp+1][n] }  (pair-interleaved along K)
__global__ __launch_bounds__(256) void pairh_kernel(
    const float* __restrict__ W, unsigned* __restrict__ Wp, int N, int total)
{
    int idx = blockIdx.x * 256 + threadIdx.x;
    if (idx >= total) return;
    int kp = idx / N, n = idx % N;
    Wp[idx] = packh2(W[(size_t)(2 * kp) * N + n], W[(size_t)(2 * kp + 1) * N + n]);
}

// QKV weights: [h,d,e] x3 -> pair-interleaved half2 [512][3072]
__global__ __launch_bounds__(256) void repackh_kernel(
    const float* __restrict__ WQ, const float* __restrict__ WK,
    const float* __restrict__ WV, const float* __restrict__ bQ,
    const float* __restrict__ bK, const float* __restrict__ bV)
{
    int idx = blockIdx.x * 256 + threadIdx.x;
    if (idx < D3) {
        g_bqkv[idx] = (idx < 1024) ? bQ[idx]
                    : (idx < 2048) ? bK[idx - 1024]
                    :                bV[idx - 2048];
    }
    if (idx >= (DRES / 2) * D3) return;
    int kp = idx / D3;
    int j  = idx % D3;
    const float* W = WQ; int jj = j;
    if (j >= 2048)      { W = WV; jj = j - 2048; }
    else if (j >= 1024) { W = WK; jj = j - 1024; }
    int base = ((jj >> 6) << 16) | (jj & 63);
    g_Wqkvh[idx] = packh2(W[base + ((2 * kp) << 6)], W[base + ((2 * kp + 1) << 6)]);
}

// ---------------- layernorm: fp32 in, fp16 out ---------------------------------
__global__ __launch_bounds__(256) void lnh_kernel(
    const float* __restrict__ x, const float* __restrict__ w,
    const float* __restrict__ b, __half* __restrict__ y)
{
    __shared__ float red[8];
    __shared__ float sMean, sRstd;
    int row = blockIdx.x, tid = threadIdx.x;
    const float* xr = x + (size_t)row * DRES;
    float4 v = ((const float4*)xr)[tid];

    float s = v.x + v.y + v.z + v.w;
    #pragma unroll
    for (int o = 16; o > 0; o >>= 1) s += __shfl_xor_sync(0xffffffffu, s, o);
    if ((tid & 31) == 0) red[tid >> 5] = s;
    __syncthreads();
    if (tid == 0) {
        float t = 0.f;
        #pragma unroll
        for (int i = 0; i < 8; i++) t += red[i];
        sMean = t * (1.f / DRES);
    }
    __syncthreads();
    float mean = sMean;
    float cx = v.x - mean, cy = v.y - mean, cz = v.z - mean, cw = v.w - mean;
    float sq = cx * cx + cy * cy + cz * cz + cw * cw;
    #pragma unroll
    for (int o = 16; o > 0; o >>= 1) sq += __shfl_xor_sync(0xffffffffu, sq, o);
    if ((tid & 31) == 0) red[tid >> 5] = sq;
    __syncthreads();
    if (tid == 0) {
        float t = 0.f;
        #pragma unroll
        for (int i = 0; i < 8; i++) t += red[i];
        sRstd = rsqrtf(t * (1.f / DRES) + 1e-5f);
    }
    __syncthreads();
    float rstd = sRstd;
    float4 wv = ((const float4*)w)[tid];
    float4 bv = ((const float4*)b)[tid];
    unsigned* yo = (unsigned*)(y + (size_t)row * DRES);
    yo[2 * tid]     = packh2(cx * rstd * wv.x + bv.x, cy * rstd * wv.y + bv.y);
    yo[2 * tid + 1] = packh2(cz * rstd * wv.z + bv.z, cw * rstd * wv.w + bv.w);
}

// ---------------- FP16 tensor-core GEMM ----------------------------------------
// C[M,N] = A[M,K](half) @ B[K,N](pair-interleaved half2) + bias (+res | gelu)
// 128x128 tile, K-tile 32 halfs, 8 warps (2m x 4n), mma.m16n8k16.f16.
// mode 0: bias -> half C ; mode 1: bias+res -> float C ; mode 2: bias+gelu -> half C
__device__ __forceinline__ float gelu_exact(float x) {
    return 0.5f * x * (1.0f + erff(x * 0.70710678118654752f));
}

#define A_STRIDE 20                               // u32 per A row (16 + 4 pad)
#define STAGE_U32 (128 * A_STRIDE + 16 * 128)     // 2560 + 2048 = 4608
#define SMEM_BYTES (2 * STAGE_U32 * 4)            // 36864

__device__ __forceinline__ void cp_async16(void* smem_dst, const void* gmem_src) {
    unsigned saddr = (unsigned)__cvta_generic_to_shared(smem_dst);
    asm volatile("cp.async.cg.shared.global [%0], [%1], 16;\n"
                 :: "r"(saddr), "l"(gmem_src));
}

__device__ __forceinline__ void load_stage_h(
    unsigned* As, unsigned* Bs,
    const unsigned* __restrict__ A32, const unsigned* __restrict__ Bp,
    int m0, int n0, int kt16, int K2, int N, int tid)
{
    // A: 128 rows x 16 kp-words
    #pragma unroll
    for (int u = 0; u < 2; u++) {
        int lin = u * 256 + tid;
        int m = lin >> 2, kq = lin & 3;
        cp_async16(As + m * A_STRIDE + kq * 4,
                   A32 + (size_t)(m0 + m) * K2 + kt16 + kq * 4);
    }
    // B: 16 kp x 128 n, xor swizzle n ^ ((kp&3)<<3)
    #pragma unroll
    for (int u = 0; u < 2; u++) {
        int lin = u * 256 + tid;
        int kp = lin >> 5, nc = (lin & 31) * 4;
        int swz = nc ^ ((kp & 3) << 3);
        cp_async16(Bs + kp * 128 + swz,
                   Bp + (size_t)(kt16 + kp) * N + n0 + nc);
    }
}

__global__ __launch_bounds__(256, 2) void hgemm_kernel(
    const __half* __restrict__ A, const unsigned* __restrict__ Bp,
    const float* __restrict__ bias, const float* __restrict__ res,
    void* __restrict__ Cv, int M, int N, int K, int mode)
{
    extern __shared__ unsigned smem[];
    const unsigned* A32 = (const unsigned*)A;
    int tid = threadIdx.x;
    int lane = tid & 31;
    int warp = tid >> 5;
    int warp_m = warp & 1;
    int warp_n = warp >> 1;
    int m0 = blockIdx.y * 128, n0 = blockIdx.x * 128;
    int K2 = K >> 1;
    int t4 = lane & 3, g8 = lane >> 2;

    float c[4][4][4];
    #pragma unroll
    for (int i = 0; i < 4; i++)
        #pragma unroll
        for (int j = 0; j < 4; j++) {
            c[i][j][0] = 0.f; c[i][j][1] = 0.f; c[i][j][2] = 0.f; c[i][j][3] = 0.f;
        }

    int KT = K >> 5;   // K-tiles of 32 halfs (16 u32)

    load_stage_h(smem, smem + 128 * A_STRIDE, A32, Bp, m0, n0, 0, K2, N, tid);
    asm volatile("cp.async.commit_group;\n");

    for (int t = 0; t < KT; t++) {
        if (t + 1 < KT) {
            unsigned* Asn = smem + ((t + 1) & 1) * STAGE_U32;
            load_stage_h(Asn, Asn + 128 * A_STRIDE, A32, Bp, m0, n0,
                         (t + 1) * 16, K2, N, tid);
        }
        asm volatile("cp.async.commit_group;\n");
        asm volatile("cp.async.wait_group 1;\n");
        __syncthreads();

        const unsigned* As = smem + (t & 1) * STAGE_U32;
        const unsigned* Bs = As + 128 * A_STRIDE;

        #pragma unroll
        for (int ks = 0; ks < 2; ks++) {
            int kpb = ks * 8;
            unsigned a[4][4];
            #pragma unroll
            for (int mt = 0; mt < 4; mt++) {
                int row = warp_m * 64 + mt * 16 + g8;
                a[mt][0] = As[row * A_STRIDE + kpb + t4];
                a[mt][1] = As[(row + 8) * A_STRIDE + kpb + t4];
                a[mt][2] = As[row * A_STRIDE + kpb + t4 + 4];
                a[mt][3] = As[(row + 8) * A_STRIDE + kpb + t4 + 4];
            }
            unsigned bfr[4][2];
            #pragma unroll
            for (int nt = 0; nt < 4; nt++) {
                int n = warp_n * 32 + nt * 8 + g8;
                int swz = n ^ (t4 << 3);   // (kp&3)==t4 for both kp and kp+4
                bfr[nt][0] = Bs[(kpb + t4) * 128 + swz];
                bfr[nt][1] = Bs[(kpb + t4 + 4) * 128 + swz];
            }
            #pragma unroll
            for (int mt = 0; mt < 4; mt++)
                #pragma unroll
                for (int nt = 0; nt < 4; nt++) {
                    asm volatile(
                        "mma.sync.aligned.m16n8k16.row.col.f32.f16.f16.f32 "
                        "{%0,%1,%2,%3}, {%4,%5,%6,%7}, {%8,%9}, {%0,%1,%2,%3};\n"
                        : "+f"(c[mt][nt][0]), "+f"(c[mt][nt][1]),
                          "+f"(c[mt][nt][2]), "+f"(c[mt][nt][3])
                        : "r"(a[mt][0]), "r"(a[mt][1]), "r"(a[mt][2]), "r"(a[mt][3]),
                          "r"(bfr[nt][0]), "r"(bfr[nt][1]));
                }
        }
        __syncthreads();
    }

    // epilogue
    #pragma unroll
    for (int mt = 0; mt < 4; mt++) {
        int r0 = m0 + warp_m * 64 + mt * 16 + g8;
        #pragma unroll
        for (int nt = 0; nt < 4; nt++) {
            int col = n0 + warp_n * 32 + nt * 8 + 2 * t4;
            float2 bb = *(const float2*)(bias + col);
            float2 v0 = make_float2(c[mt][nt][0] + bb.x, c[mt][nt][1] + bb.y);
            float2 v1 = make_float2(c[mt][nt][2] + bb.x, c[mt][nt][3] + bb.y);
            if (mode == 1) {
                float* C = (float*)Cv;
                float2 ra = *(const float2*)(res + (size_t)r0 * N + col);
                float2 rb = *(const float2*)(res + (size_t)(r0 + 8) * N + col);
                v0.x += ra.x; v0.y += ra.y;
                v1.x += rb.x; v1.y += rb.y;
                *(float2*)(C + (size_t)r0 * N + col) = v0;
                *(float2*)(C + (size_t)(r0 + 8) * N + col) = v1;
            } else {
                if (mode == 2) {
                    v0.x = gelu_exact(v0.x); v0.y = gelu_exact(v0.y);
                    v1.x = gelu_exact(v1.x); v1.y = gelu_exact(v1.y);
                }
                unsigned* C = (unsigned*)Cv;
                C[((size_t)r0 * N + col) >> 1]       = packh2(v0.x, v0.y);
                C[((size_t)(r0 + 8) * N + col) >> 1] = packh2(v1.x, v1.y);
            }
        }
    }
}

// ---------------- fp16 tensor-core flash attention -----------------------------
// Br=128 (8 warps x 16 rows), Bc=64. Both S and P*V via mma.m16n8k16.f16.
#define KSP 36   // u32 per Ks row (32 + 4 pad): conflict-free
#define VSP 36   // u32 per Vt row

__global__ __launch_bounds__(256) void attnh_kernel(
    const __half* __restrict__ qkv, __half* __restrict__ z)
{
    __shared__ unsigned Ks[64 * KSP];   // [key][dimpair] half2 (natural pairs)
    __shared__ unsigned Vt[64 * VSP];   // [dim][keypair]  half2 (transposed)

    int q0 = blockIdx.x * 128;
    int h  = blockIdx.y, b = blockIdx.z;
    int tid = threadIdx.x, lane = tid & 31, w = tid >> 5;
    int t4 = lane & 3, g8 = lane >> 2;

    const unsigned* qb32 = (const unsigned*)(qkv + (size_t)b * SEQ * D3) + h * 32;
    const unsigned* kb32 = qb32 + 512;    // +1024 halfs
    const unsigned* vb32 = qb32 + 1024;   // +2048 halfs
    const int RS = D3 / 2;                // u32 row stride (1536)

    int row0 = q0 + w * 16 + g8;

    // Q fragments (half2 pairs straight from gmem, scaled by 1/8)
    __half2 scale = __float2half2_rn(0.125f);
    unsigned qa[4][4];
    {
        const unsigned* r0p = qb32 + (size_t)row0 * RS;
        const unsigned* r8p = qb32 + (size_t)(row0 + 8) * RS;
        #pragma unroll
        for (int kb = 0; kb < 4; kb++) {
            int kp = kb * 8 + t4;
            __half2 x0 = __hmul2(*(const __half2*)&r0p[kp], scale);
            __half2 x1 = __hmul2(*(const __half2*)&r8p[kp], scale);
            __half2 x2 = __hmul2(*(const __half2*)&r0p[kp + 4], scale);
            __half2 x3 = __hmul2(*(const __half2*)&r8p[kp + 4], scale);
            qa[kb][0] = *(unsigned*)&x0;
            qa[kb][1] = *(unsigned*)&x1;
            qa[kb][2] = *(unsigned*)&x2;
            qa[kb][3] = *(unsigned*)&x3;
        }
    }

    float m0 = -1e30f, m1 = -1e30f, l0 = 0.f, l1 = 0.f;
    float o[8][4];
    #pragma unroll
    for (int nb = 0; nb < 8; nb++) {
        o[nb][0] = 0.f; o[nb][1] = 0.f; o[nb][2] = 0.f; o[nb][3] = 0.f;
    }

    int ntiles = (q0 >> 6) + 2;
    for (int t = 0; t < ntiles; t++) {
        int j0 = t * 64;
        __syncthreads();
        // K tile: straight vector copy, 64 keys x 32 pair-words
        #pragma unroll
        for (int u = 0; u < 2; u++) {
            int lin = u * 256 + tid;
            int key = lin >> 3, kq = lin & 7;
            uint4 kv = *(const uint4*)(kb32 + (size_t)(j0 + key) * RS + kq * 4);
            *(uint4*)&Ks[key * KSP + kq * 4] = kv;
        }
        // V tile transposed: Vt[dim][kp] = {V[2kp][dim], V[2kp+1][dim]}
        {
            int eg = tid >> 5, kp = tid & 31;   // eg: 8 dims, kp: key pair
            uint4 va = *(const uint4*)(vb32 + (size_t)(j0 + 2 * kp) * RS + eg * 4);
            uint4 vc = *(const uint4*)(vb32 + (size_t)(j0 + 2 * kp + 1) * RS + eg * 4);
            unsigned* dst = &Vt[(eg * 8) * VSP + kp];
            dst[0 * VSP] = __byte_perm(va.x, vc.x, 0x5410);
            dst[1 * VSP] = __byte_perm(va.x, vc.x, 0x7632);
            dst[2 * VSP] = __byte_perm(va.y, vc.y, 0x5410);
            dst[3 * VSP] = __byte_perm(va.y, vc.y, 0x7632);
            dst[4 * VSP] = __byte_perm(va.z, vc.z, 0x5410);
            dst[5 * VSP] = __byte_perm(va.z, vc.z, 0x7632);
            dst[6 * VSP] = __byte_perm(va.w, vc.w, 0x5410);
            dst[7 * VSP] = __byte_perm(va.w, vc.w, 0x7632);
        }
        __syncthreads();

        // S = (Q/8) K^T : 8 n-blocks x 4 k16-steps
        float c[8][4];
        #pragma unroll
        for (int nb = 0; nb < 8; nb++) {
            c[nb][0] = 0.f; c[nb][1] = 0.f; c[nb][2] = 0.f; c[nb][3] = 0.f;
            const unsigned* krow = &Ks[(nb * 8 + g8) * KSP + t4];
            #pragma unroll
            for (int kb = 0; kb < 4; kb++) {
                unsigned b0 = krow[kb * 8];
                unsigned b1 = krow[kb * 8 + 4];
                asm volatile(
                    "mma.sync.aligned.m16n8k16.row.col.f32.f16.f16.f32 "
                    "{%0,%1,%2,%3}, {%4,%5,%6,%7}, {%8,%9}, {%0,%1,%2,%3};\n"
                    : "+f"(c[nb][0]), "+f"(c[nb][1]), "+f"(c[nb][2]), "+f"(c[nb][3])
                    : "r"(qa[kb][0]), "r"(qa[kb][1]), "r"(qa[kb][2]), "r"(qa[kb][3]),
                      "r"(b0), "r"(b1));
            }
        }

        // causal mask (near-diagonal tiles only)
        if (j0 + 63 > q0 + w * 16) {
            #pragma unroll
            for (int nb = 0; nb < 8; nb++) {
                int key = j0 + nb * 8 + 2 * t4;
                if (key > row0)         c[nb][0] = -1e30f;
                if (key + 1 > row0)     c[nb][1] = -1e30f;
                if (key > row0 + 8)     c[nb][2] = -1e30f;
                if (key + 1 > row0 + 8) c[nb][3] = -1e30f;
            }
        }

        // online softmax (row's 64 scores live in a 4-lane quad)
        float mt0 = -1e30f, mt1 = -1e30f;
        #pragma unroll
        for (int nb = 0; nb < 8; nb++) {
            mt0 = fmaxf(mt0, fmaxf(c[nb][0], c[nb][1]));
            mt1 = fmaxf(mt1, fmaxf(c[nb][2], c[nb][3]));
        }
        mt0 = fmaxf(mt0, __shfl_xor_sync(0xffffffffu, mt0, 1));
        mt0 = fmaxf(mt0, __shfl_xor_sync(0xffffffffu, mt0, 2));
        mt1 = fmaxf(mt1, __shfl_xor_sync(0xffffffffu, mt1, 1));
        mt1 = fmaxf(mt1, __shfl_xor_sync(0xffffffffu, mt1, 2));

        float mn0 = fmaxf(m0, mt0), mn1 = fmaxf(m1, mt1);
        float al0 = __expf(m0 - mn0), al1 = __expf(m1 - mn1);
        m0 = mn0; m1 = mn1;

        float rs0 = 0.f, rs1 = 0.f;
        #pragma unroll
        for (int nb = 0; nb < 8; nb++) {
            c[nb][0] = __expf(c[nb][0] - mn0);
            c[nb][1] = __expf(c[nb][1] - mn0);
            c[nb][2] = __expf(c[nb][2] - mn1);
            c[nb][3] = __expf(c[nb][3] - mn1);
            rs0 += c[nb][0] + c[nb][1];
            rs1 += c[nb][2] + c[nb][3];
        }
        rs0 += __shfl_xor_sync(0xffffffffu, rs0, 1);
        rs0 += __shfl_xor_sync(0xffffffffu, rs0, 2);
        rs1 += __shfl_xor_sync(0xffffffffu, rs1, 1);
        rs1 += __shfl_xor_sync(0xffffffffu, rs1, 2);
        l0 = l0 * al0 + rs0;
        l1 = l1 * al1 + rs1;

        #pragma unroll
        for (int nb = 0; nb < 8; nb++) {
            o[nb][0] *= al0; o[nb][1] *= al0;
            o[nb][2] *= al1; o[nb][3] *= al1;
        }

        // pack P into fp16 a-fragments
        unsigned pa[4][4];
        #pragma unroll
        for (int kb2 = 0; kb2 < 4; kb2++) {
            pa[kb2][0] = packh2(c[2 * kb2][0],     c[2 * kb2][1]);
            pa[kb2][1] = packh2(c[2 * kb2][2],     c[2 * kb2][3]);
            pa[kb2][2] = packh2(c[2 * kb2 + 1][0], c[2 * kb2 + 1][1]);
            pa[kb2][3] = packh2(c[2 * kb2 + 1][2], c[2 * kb2 + 1][3]);
        }

        // O += P @ V
        #pragma unroll
        for (int nb = 0; nb < 8; nb++) {
            const unsigned* vrow = &Vt[(nb * 8 + g8) * VSP + t4];
            #pragma unroll
            for (int kb2 = 0; kb2 < 4; kb2++) {
                unsigned b0 = vrow[kb2 * 8];
                unsigned b1 = vrow[kb2 * 8 + 4];
                asm volatile(
                    "mma.sync.aligned.m16n8k16.row.col.f32.f16.f16.f32 "
                    "{%0,%1,%2,%3}, {%4,%5,%6,%7}, {%8,%9}, {%0,%1,%2,%3};\n"
                    : "+f"(o[nb][0]), "+f"(o[nb][1]), "+f"(o[nb][2]), "+f"(o[nb][3])
                    : "r"(pa[kb2][0]), "r"(pa[kb2][1]), "r"(pa[kb2][2]), "r"(pa[kb2][3]),
                      "r"(b0), "r"(b1));
            }
        }
    }

    // epilogue: normalize, store fp16
    float inv0 = 1.f / l0, inv1 = 1.f / l1;
    unsigned* z32 = (unsigned*)z;
    size_t zr0 = (((size_t)b * SEQ + row0) * DRES + h * 64) >> 1;
    size_t zr8 = zr0 + 4 * DRES;
    #pragma unroll
    for (int nb = 0; nb < 8; nb++) {
        int cp = (nb * 8 + 2 * t4) >> 1;
        z32[zr0 + cp] = packh2(o[nb][0] * inv0, o[nb][1] * inv0);
        z32[zr8 + cp] = packh2(o[nb][2] * inv1, o[nb][3] * inv1);
    }
}

// ---------------- launch --------------------------------------------------------
extern "C" void kernel_launch(void* const* d_in, const int* in_sizes, int n_in,
                              void* d_out, int out_size)
{
    const float* resid_pre = (const float*)d_in[0];
    const float* ln1_w     = (const float*)d_in[1];
    const float* ln1_b     = (const float*)d_in[2];
    const float* WQ        = (const float*)d_in[3];
    const float* bQ        = (const float*)d_in[4];
    const float* WK        = (const float*)d_in[5];
    const float* bK        = (const float*)d_in[6];
    const float* WV        = (const float*)d_in[7];
    const float* bV        = (const float*)d_in[8];
    const float* WO        = (const float*)d_in[9];
    const float* bO        = (const float*)d_in[10];
    const float* ln2_w     = (const float*)d_in[11];
    const float* ln2_b     = (const float*)d_in[12];
    const float* Win       = (const float*)d_in[13];
    const float* bin       = (const float*)d_in[14];
    const float* Wout      = (const float*)d_in[15];
    const float* bout      = (const float*)d_in[16];
    float* out = (float*)d_out;

    __half *xh, *qkvh, *zh, *mlph;
    float *rm, *bqkv;
    unsigned *Wqkvh, *WOh, *Winh, *Wouth;
    cudaGetSymbolAddress((void**)&xh,    g_xh);
    cudaGetSymbolAddress((void**)&qkvh,  g_qkvh);
    cudaGetSymbolAddress((void**)&zh,    g_zh);
    cudaGetSymbolAddress((void**)&mlph,  g_mlph);
    cudaGetSymbolAddress((void**)&rm,    g_rm);
    cudaGetSymbolAddress((void**)&bqkv,  g_bqkv);
    cudaGetSymbolAddress((void**)&Wqkvh, g_Wqkvh);
    cudaGetSymbolAddress((void**)&WOh,   g_WOh);
    cudaGetSymbolAddress((void**)&Winh,  g_Winh);
    cudaGetSymbolAddress((void**)&Wouth, g_Wouth);

    cudaFuncSetAttribute(hgemm_kernel,
                         cudaFuncAttributeMaxDynamicSharedMemorySize, SMEM_BYTES);

    // weight prep: repack QKV + pair-interleave all weights into fp16
    repackh_kernel<<<((DRES / 2) * D3) / 256, 256>>>(WQ, WK, WV, bQ, bK, bV);
    pairh_kernel<<<((DRES / 2) * DRES) / 256, 256>>>(WO,   WOh,   DRES, (DRES / 2) * DRES);
    pairh_kernel<<<((DRES / 2) * DMLP) / 256, 256>>>(Win,  Winh,  DMLP, (DRES / 2) * DMLP);
    pairh_kernel<<<((DMLP / 2) * DRES) / 256, 256>>>(Wout, Wouth, DRES, (DMLP / 2) * DRES);

    // LN1 -> fp16
    lnh_kernel<<<T_TOK, 256>>>(resid_pre, ln1_w, ln1_b, xh);

    // QKV projection -> fp16 qkv
    hgemm_kernel<<<dim3(D3 / 128, T_TOK / 128), 256, SMEM_BYTES>>>(
        xh, Wqkvh, bqkv, nullptr, qkvh, T_TOK, D3, DRES, 0);

    // fp16 tensor-core causal flash attention
    attnh_kernel<<<dim3(SEQ / 128, NH, 2), 256>>>(qkvh, zh);

    // O projection + residual -> fp32 resid_mid (exact residual)
    hgemm_kernel<<<dim3(DRES / 128, T_TOK / 128), 256, SMEM_BYTES>>>(
        zh, WOh, bO, resid_pre, rm, T_TOK, DRES, DRES, 1);

    // LN2 -> fp16
    lnh_kernel<<<T_TOK, 256>>>(rm, ln2_w, ln2_b, xh);

    // MLP in + exact GELU -> fp16 hidden
    hgemm_kernel<<<dim3(DMLP / 128, T_TOK / 128), 256, SMEM_BYTES>>>(
        xh, Winh, bin, nullptr, mlph, T_TOK, DMLP, DRES, 2);

    // MLP out + residual -> final fp32 output
    hgemm_kernel<<<dim3(DRES / 128, T_TOK / 128), 256, SMEM_BYTES>>>(
        mlph, Wouth, bout, rm, out, T_TOK, DRES, DMLP, 1);
}

// round 13
// speedup vs baseline: 7.1365x; 1.1069x over previous
#include <cuda_runtime.h>
#include <cuda_fp16.h>
#include <math.h>

#define T_TOK 4096
#define SEQ   2048
#define DRES  1024
#define D3    3072
#define DMLP  4096
#define NH    16

// ---------------- device scratch ----------------------------------------------
__device__ __half  g_xh [(size_t)T_TOK * DRES];    // LN output (fp16)
__device__ __half  g_qkvh[(size_t)T_TOK * D3];     // QKV (fp16)
__device__ __half  g_zh [(size_t)T_TOK * DRES];    // attention out (fp16)
__device__ __half  g_mlph[(size_t)T_TOK * DMLP];   // MLP hidden post-gelu (fp16)
__device__ float   g_rm [(size_t)T_TOK * DRES];    // resid_mid (fp32, exact)
__device__ float    g_bqkv[D3];
__device__ unsigned g_Wqkvh[(size_t)(DRES / 2) * D3];   // pair-interleaved half2
__device__ unsigned g_WOh  [(size_t)(DRES / 2) * DRES];
__device__ unsigned g_Winh [(size_t)(DRES / 2) * DMLP];
__device__ unsigned g_Wouth[(size_t)(DMLP / 2) * DRES];

__device__ __forceinline__ unsigned packh2(float a, float b) {
    __half2 h = __floats2half2_rn(a, b);
    return *(unsigned*)&h;
}

// ---------------- weight converts (vectorized) ---------------------------------
// Wp[kp][n] = half2{ W[2kp][n], W[2kp+1][n] }; 4 n per thread.
__global__ __launch_bounds__(256) void pairh4_kernel(
    const float* __restrict__ W, uint4* __restrict__ Wp4, int N, int total4)
{
    int idx = blockIdx.x * 256 + threadIdx.x;
    if (idx >= total4) return;
    int N4 = N >> 2;
    int kp = idx / N4, n = (idx % N4) << 2;
    const float4 r0 = *(const float4*)(W + (size_t)(2 * kp) * N + n);
    const float4 r1 = *(const float4*)(W + (size_t)(2 * kp + 1) * N + n);
    uint4 o;
    o.x = packh2(r0.x, r1.x);
    o.y = packh2(r0.y, r1.y);
    o.z = packh2(r0.z, r1.z);
    o.w = packh2(r0.w, r1.w);
    Wp4[idx] = o;
}

// QKV weights: [h,d,e] x3 -> pair-interleaved half2 [512][3072]
__global__ __launch_bounds__(256) void repackh_kernel(
    const float* __restrict__ WQ, const float* __restrict__ WK,
    const float* __restrict__ WV, const float* __restrict__ bQ,
    const float* __restrict__ bK, const float* __restrict__ bV)
{
    int idx = blockIdx.x * 256 + threadIdx.x;
    if (idx < D3) {
        g_bqkv[idx] = (idx < 1024) ? bQ[idx]
                    : (idx < 2048) ? bK[idx - 1024]
                    :                bV[idx - 2048];
    }
    if (idx >= (DRES / 2) * D3) return;
    int kp = idx / D3;
    int j  = idx % D3;
    const float* W = WQ; int jj = j;
    if (j >= 2048)      { W = WV; jj = j - 2048; }
    else if (j >= 1024) { W = WK; jj = j - 1024; }
    int base = ((jj >> 6) << 16) | (jj & 63);
    g_Wqkvh[idx] = packh2(W[base + ((2 * kp) << 6)], W[base + ((2 * kp + 1) << 6)]);
}

// ---------------- layernorm: fp32 in, fp16 out ---------------------------------
__global__ __launch_bounds__(256) void lnh_kernel(
    const float* __restrict__ x, const float* __restrict__ w,
    const float* __restrict__ b, __half* __restrict__ y)
{
    __shared__ float red[8];
    __shared__ float sMean, sRstd;
    int row = blockIdx.x, tid = threadIdx.x;
    const float* xr = x + (size_t)row * DRES;
    float4 v = ((const float4*)xr)[tid];

    float s = v.x + v.y + v.z + v.w;
    #pragma unroll
    for (int o = 16; o > 0; o >>= 1) s += __shfl_xor_sync(0xffffffffu, s, o);
    if ((tid & 31) == 0) red[tid >> 5] = s;
    __syncthreads();
    if (tid == 0) {
        float t = 0.f;
        #pragma unroll
        for (int i = 0; i < 8; i++) t += red[i];
        sMean = t * (1.f / DRES);
    }
    __syncthreads();
    float mean = sMean;
    float cx = v.x - mean, cy = v.y - mean, cz = v.z - mean, cw = v.w - mean;
    float sq = cx * cx + cy * cy + cz * cz + cw * cw;
    #pragma unroll
    for (int o = 16; o > 0; o >>= 1) sq += __shfl_xor_sync(0xffffffffu, sq, o);
    if ((tid & 31) == 0) red[tid >> 5] = sq;
    __syncthreads();
    if (tid == 0) {
        float t = 0.f;
        #pragma unroll
        for (int i = 0; i < 8; i++) t += red[i];
        sRstd = rsqrtf(t * (1.f / DRES) + 1e-5f);
    }
    __syncthreads();
    float rstd = sRstd;
    float4 wv = ((const float4*)w)[tid];
    float4 bv = ((const float4*)b)[tid];
    unsigned* yo = (unsigned*)(y + (size_t)row * DRES);
    yo[2 * tid]     = packh2(cx * rstd * wv.x + bv.x, cy * rstd * wv.y + bv.y);
    yo[2 * tid + 1] = packh2(cz * rstd * wv.z + bv.z, cw * rstd * wv.w + bv.w);
}

// ---------------- FP16 tensor-core GEMM (mma.sync, sm_80-era PTX only) ---------
// C[M,N] = A[M,K](half) @ B[K,N](pair-interleaved half2) + bias (+res | gelu)
// 128x128 tile, K-tile 64 halfs (32 u32), 8 warps (2m x 4n), 3-stage cp.async,
// A-fragments via ldmatrix.x4.
__device__ __forceinline__ float gelu_exact(float x) {
    return 0.5f * x * (1.0f + erff(x * 0.70710678118654752f));
}

#define A_STRIDE 36                               // u32 per A row (32 + 4 pad)
#define A_U32 (128 * A_STRIDE)                    // 4608
#define B_U32 (32 * 128)                          // 4096
#define STAGE_U32 (A_U32 + B_U32)                 // 8704
#define SMEM_BYTES (3 * STAGE_U32 * 4)            // 104448

__device__ __forceinline__ void cp_async16(void* smem_dst, const void* gmem_src) {
    unsigned saddr = (unsigned)__cvta_generic_to_shared(smem_dst);
    asm volatile("cp.async.cg.shared.global [%0], [%1], 16;\n"
                 :: "r"(saddr), "l"(gmem_src));
}
__device__ __forceinline__ void ldsm4(unsigned r[4], unsigned saddr) {
    asm volatile(
        "ldmatrix.sync.aligned.m8n8.x4.shared.b16 {%0,%1,%2,%3}, [%4];"
        : "=r"(r[0]), "=r"(r[1]), "=r"(r[2]), "=r"(r[3]) : "r"(saddr));
}

__device__ __forceinline__ void load_stage_h(
    unsigned* As, unsigned* Bs,
    const unsigned* __restrict__ A32, const unsigned* __restrict__ Bp,
    int m0, int n0, int kt32, int K2, int N, int tid)
{
    // A: 128 rows x 32 kp-words (8 x 16B chunks per row)
    #pragma unroll
    for (int u = 0; u < 4; u++) {
        int lin = u * 256 + tid;
        int m = lin >> 3, kq = lin & 7;
        cp_async16(As + m * A_STRIDE + kq * 4,
                   A32 + (size_t)(m0 + m) * K2 + kt32 + kq * 4);
    }
    // B: 32 kp x 128 n, xor swizzle n ^ ((kp&3)<<3)
    #pragma unroll
    for (int u = 0; u < 4; u++) {
        int lin = u * 256 + tid;
        int kp = lin >> 5, nc = (lin & 31) * 4;
        int swz = nc ^ ((kp & 3) << 3);
        cp_async16(Bs + kp * 128 + swz,
                   Bp + (size_t)(kt32 + kp) * N + n0 + nc);
    }
}

__global__ __launch_bounds__(256, 2) void hgemm_kernel(
    const __half* __restrict__ A, const unsigned* __restrict__ Bp,
    const float* __restrict__ bias, const float* __restrict__ res,
    void* __restrict__ Cv, int M, int N, int K, int mode)
{
    extern __shared__ unsigned smem[];
    const unsigned* A32 = (const unsigned*)A;
    int tid = threadIdx.x;
    int lane = tid & 31;
    int warp = tid >> 5;
    int warp_m = warp & 1;
    int warp_n = warp >> 1;
    int m0 = blockIdx.y * 128, n0 = blockIdx.x * 128;
    int K2 = K >> 1;
    int t4 = lane & 3, g8 = lane >> 2;

    // ldmatrix per-lane source row/col offsets within the A tile
    int lrow = warp_m * 64 + (lane & 7) + ((lane >> 3) & 1) * 8;
    int lcol = ((lane >> 4) & 1) * 4;
    unsigned sbase = (unsigned)__cvta_generic_to_shared(smem);
    unsigned aoff = (lrow * A_STRIDE + lcol) * 4;   // bytes

    float c[4][4][4];
    #pragma unroll
    for (int i = 0; i < 4; i++)
        #pragma unroll
        for (int j = 0; j < 4; j++) {
            c[i][j][0] = 0.f; c[i][j][1] = 0.f; c[i][j][2] = 0.f; c[i][j][3] = 0.f;
        }

    int KT = K >> 6;   // K-tiles of 64 halfs (32 u32)

    // prologue: stages 0 and 1
    load_stage_h(smem, smem + A_U32, A32, Bp, m0, n0, 0, K2, N, tid);
    asm volatile("cp.async.commit_group;\n");
    load_stage_h(smem + STAGE_U32, smem + STAGE_U32 + A_U32, A32, Bp,
                 m0, n0, 32, K2, N, tid);
    asm volatile("cp.async.commit_group;\n");

    for (int t = 0; t < KT; t++) {
        if (t + 2 < KT) {
            unsigned* Asn = smem + ((t + 2) % 3) * STAGE_U32;
            load_stage_h(Asn, Asn + A_U32, A32, Bp, m0, n0,
                         (t + 2) * 32, K2, N, tid);
        }
        asm volatile("cp.async.commit_group;\n");
        asm volatile("cp.async.wait_group 2;\n");
        __syncthreads();

        int buf = t % 3;
        const unsigned* As = smem + buf * STAGE_U32;
        const unsigned* Bs = As + A_U32;
        unsigned abase = sbase + buf * (STAGE_U32 * 4) + aoff;

        #pragma unroll
        for (int ks = 0; ks < 4; ks++) {
            int kpb = ks * 8;
            unsigned a[4][4];
            #pragma unroll
            for (int mt = 0; mt < 4; mt++)
                ldsm4(a[mt], abase + (mt * 16 * A_STRIDE + kpb) * 4);
            unsigned bfr[4][2];
            #pragma unroll
            for (int nt = 0; nt < 4; nt++) {
                int n = warp_n * 32 + nt * 8 + g8;
                int swz = n ^ (t4 << 3);   // (kp&3)==t4 for kp and kp+4
                bfr[nt][0] = Bs[(kpb + t4) * 128 + swz];
                bfr[nt][1] = Bs[(kpb + t4 + 4) * 128 + swz];
            }
            #pragma unroll
            for (int mt = 0; mt < 4; mt++)
                #pragma unroll
                for (int nt = 0; nt < 4; nt++) {
                    asm volatile(
                        "mma.sync.aligned.m16n8k16.row.col.f32.f16.f16.f32 "
                        "{%0,%1,%2,%3}, {%4,%5,%6,%7}, {%8,%9}, {%0,%1,%2,%3};\n"
                        : "+f"(c[mt][nt][0]), "+f"(c[mt][nt][1]),
                          "+f"(c[mt][nt][2]), "+f"(c[mt][nt][3])
                        : "r"(a[mt][0]), "r"(a[mt][1]), "r"(a[mt][2]), "r"(a[mt][3]),
                          "r"(bfr[nt][0]), "r"(bfr[nt][1]));
                }
        }
        __syncthreads();
    }

    // epilogue
    #pragma unroll
    for (int mt = 0; mt < 4; mt++) {
        int r0 = m0 + warp_m * 64 + mt * 16 + g8;
        #pragma unroll
        for (int nt = 0; nt < 4; nt++) {
            int col = n0 + warp_n * 32 + nt * 8 + 2 * t4;
            float2 bb = *(const float2*)(bias + col);
            float2 v0 = make_float2(c[mt][nt][0] + bb.x, c[mt][nt][1] + bb.y);
            float2 v1 = make_float2(c[mt][nt][2] + bb.x, c[mt][nt][3] + bb.y);
            if (mode == 1) {
                float* C = (float*)Cv;
                float2 ra = *(const float2*)(res + (size_t)r0 * N + col);
                float2 rb = *(const float2*)(res + (size_t)(r0 + 8) * N + col);
                v0.x += ra.x; v0.y += ra.y;
                v1.x += rb.x; v1.y += rb.y;
                *(float2*)(C + (size_t)r0 * N + col) = v0;
                *(float2*)(C + (size_t)(r0 + 8) * N + col) = v1;
            } else {
                if (mode == 2) {
                    v0.x = gelu_exact(v0.x); v0.y = gelu_exact(v0.y);
                    v1.x = gelu_exact(v1.x); v1.y = gelu_exact(v1.y);
                }
                unsigned* C = (unsigned*)Cv;
                C[((size_t)r0 * N + col) >> 1]       = packh2(v0.x, v0.y);
                C[((size_t)(r0 + 8) * N + col) >> 1] = packh2(v1.x, v1.y);
            }
        }
    }
}

// ---------------- fp16 tensor-core flash attention -----------------------------
// Br=128 (8 warps x 16 rows), Bc=64. Both S and P*V via mma.m16n8k16.f16.
#define KSP 36   // u32 per Ks row (32 + 4 pad): conflict-free
#define VSP 36   // u32 per Vt row

__global__ __launch_bounds__(256) void attnh_kernel(
    const __half* __restrict__ qkv, __half* __restrict__ z)
{
    __shared__ unsigned Ks[64 * KSP];   // [key][dimpair] half2 (natural pairs)
    __shared__ unsigned Vt[64 * VSP];   // [dim][keypair]  half2 (transposed)

    int q0 = blockIdx.x * 128;
    int h  = blockIdx.y, b = blockIdx.z;
    int tid = threadIdx.x, lane = tid & 31, w = tid >> 5;
    int t4 = lane & 3, g8 = lane >> 2;

    const unsigned* qb32 = (const unsigned*)(qkv + (size_t)b * SEQ * D3) + h * 32;
    const unsigned* kb32 = qb32 + 512;
    const unsigned* vb32 = qb32 + 1024;
    const int RS = D3 / 2;

    int row0 = q0 + w * 16 + g8;

    __half2 scale = __float2half2_rn(0.125f);
    unsigned qa[4][4];
    {
        const unsigned* r0p = qb32 + (size_t)row0 * RS;
        const unsigned* r8p = qb32 + (size_t)(row0 + 8) * RS;
        #pragma unroll
        for (int kb = 0; kb < 4; kb++) {
            int kp = kb * 8 + t4;
            __half2 x0 = __hmul2(*(const __half2*)&r0p[kp], scale);
            __half2 x1 = __hmul2(*(const __half2*)&r8p[kp], scale);
            __half2 x2 = __hmul2(*(const __half2*)&r0p[kp + 4], scale);
            __half2 x3 = __hmul2(*(const __half2*)&r8p[kp + 4], scale);
            qa[kb][0] = *(unsigned*)&x0;
            qa[kb][1] = *(unsigned*)&x1;
            qa[kb][2] = *(unsigned*)&x2;
            qa[kb][3] = *(unsigned*)&x3;
        }
    }

    float m0 = -1e30f, m1 = -1e30f, l0 = 0.f, l1 = 0.f;
    float o[8][4];
    #pragma unroll
    for (int nb = 0; nb < 8; nb++) {
        o[nb][0] = 0.f; o[nb][1] = 0.f; o[nb][2] = 0.f; o[nb][3] = 0.f;
    }

    int ntiles = (q0 >> 6) + 2;
    for (int t = 0; t < ntiles; t++) {
        int j0 = t * 64;
        __syncthreads();
        #pragma unroll
        for (int u = 0; u < 2; u++) {
            int lin = u * 256 + tid;
            int key = lin >> 3, kq = lin & 7;
            uint4 kv = *(const uint4*)(kb32 + (size_t)(j0 + key) * RS + kq * 4);
            *(uint4*)&Ks[key * KSP + kq * 4] = kv;
        }
        {
            int eg = tid >> 5, kp = tid & 31;
            uint4 va = *(const uint4*)(vb32 + (size_t)(j0 + 2 * kp) * RS + eg * 4);
            uint4 vc = *(const uint4*)(vb32 + (size_t)(j0 + 2 * kp + 1) * RS + eg * 4);
            unsigned* dst = &Vt[(eg * 8) * VSP + kp];
            dst[0 * VSP] = __byte_perm(va.x, vc.x, 0x5410);
            dst[1 * VSP] = __byte_perm(va.x, vc.x, 0x7632);
            dst[2 * VSP] = __byte_perm(va.y, vc.y, 0x5410);
            dst[3 * VSP] = __byte_perm(va.y, vc.y, 0x7632);
            dst[4 * VSP] = __byte_perm(va.z, vc.z, 0x5410);
            dst[5 * VSP] = __byte_perm(va.z, vc.z, 0x7632);
            dst[6 * VSP] = __byte_perm(va.w, vc.w, 0x5410);
            dst[7 * VSP] = __byte_perm(va.w, vc.w, 0x7632);
        }
        __syncthreads();

        float c[8][4];
        #pragma unroll
        for (int nb = 0; nb < 8; nb++) {
            c[nb][0] = 0.f; c[nb][1] = 0.f; c[nb][2] = 0.f; c[nb][3] = 0.f;
            const unsigned* krow = &Ks[(nb * 8 + g8) * KSP + t4];
            #pragma unroll
            for (int kb = 0; kb < 4; kb++) {
                unsigned b0 = krow[kb * 8];
                unsigned b1 = krow[kb * 8 + 4];
                asm volatile(
                    "mma.sync.aligned.m16n8k16.row.col.f32.f16.f16.f32 "
                    "{%0,%1,%2,%3}, {%4,%5,%6,%7}, {%8,%9}, {%0,%1,%2,%3};\n"
                    : "+f"(c[nb][0]), "+f"(c[nb][1]), "+f"(c[nb][2]), "+f"(c[nb][3])
                    : "r"(qa[kb][0]), "r"(qa[kb][1]), "r"(qa[kb][2]), "r"(qa[kb][3]),
                      "r"(b0), "r"(b1));
            }
        }

        if (j0 + 63 > q0 + w * 16) {
            #pragma unroll
            for (int nb = 0; nb < 8; nb++) {
                int key = j0 + nb * 8 + 2 * t4;
                if (key > row0)         c[nb][0] = -1e30f;
                if (key + 1 > row0)     c[nb][1] = -1e30f;
                if (key > row0 + 8)     c[nb][2] = -1e30f;
                if (key + 1 > row0 + 8) c[nb][3] = -1e30f;
            }
        }

        float mt0 = -1e30f, mt1 = -1e30f;
        #pragma unroll
        for (int nb = 0; nb < 8; nb++) {
            mt0 = fmaxf(mt0, fmaxf(c[nb][0], c[nb][1]));
            mt1 = fmaxf(mt1, fmaxf(c[nb][2], c[nb][3]));
        }
        mt0 = fmaxf(mt0, __shfl_xor_sync(0xffffffffu, mt0, 1));
        mt0 = fmaxf(mt0, __shfl_xor_sync(0xffffffffu, mt0, 2));
        mt1 = fmaxf(mt1, __shfl_xor_sync(0xffffffffu, mt1, 1));
        mt1 = fmaxf(mt1, __shfl_xor_sync(0xffffffffu, mt1, 2));

        float mn0 = fmaxf(m0, mt0), mn1 = fmaxf(m1, mt1);
        float al0 = __expf(m0 - mn0), al1 = __expf(m1 - mn1);
        m0 = mn0; m1 = mn1;

        float rs0 = 0.f, rs1 = 0.f;
        #pragma unroll
        for (int nb = 0; nb < 8; nb++) {
            c[nb][0] = __expf(c[nb][0] - mn0);
            c[nb][1] = __expf(c[nb][1] - mn0);
            c[nb][2] = __expf(c[nb][2] - mn1);
            c[nb][3] = __expf(c[nb][3] - mn1);
            rs0 += c[nb][0] + c[nb][1];
            rs1 += c[nb][2] + c[nb][3];
        }
        rs0 += __shfl_xor_sync(0xffffffffu, rs0, 1);
        rs0 += __shfl_xor_sync(0xffffffffu, rs0, 2);
        rs1 += __shfl_xor_sync(0xffffffffu, rs1, 1);
        rs1 += __shfl_xor_sync(0xffffffffu, rs1, 2);
        l0 = l0 * al0 + rs0;
        l1 = l1 * al1 + rs1;

        #pragma unroll
        for (int nb = 0; nb < 8; nb++) {
            o[nb][0] *= al0; o[nb][1] *= al0;
            o[nb][2] *= al1; o[nb][3] *= al1;
        }

        unsigned pa[4][4];
        #pragma unroll
        for (int kb2 = 0; kb2 < 4; kb2++) {
            pa[kb2][0] = packh2(c[2 * kb2][0],     c[2 * kb2][1]);
            pa[kb2][1] = packh2(c[2 * kb2][2],     c[2 * kb2][3]);
            pa[kb2][2] = packh2(c[2 * kb2 + 1][0], c[2 * kb2 + 1][1]);
            pa[kb2][3] = packh2(c[2 * kb2 + 1][2], c[2 * kb2 + 1][3]);
        }

        #pragma unroll
        for (int nb = 0; nb < 8; nb++) {
            const unsigned* vrow = &Vt[(nb * 8 + g8) * VSP + t4];
            #pragma unroll
            for (int kb2 = 0; kb2 < 4; kb2++) {
                unsigned b0 = vrow[kb2 * 8];
                unsigned b1 = vrow[kb2 * 8 + 4];
                asm volatile(
                    "mma.sync.aligned.m16n8k16.row.col.f32.f16.f16.f32 "
                    "{%0,%1,%2,%3}, {%4,%5,%6,%7}, {%8,%9}, {%0,%1,%2,%3};\n"
                    : "+f"(o[nb][0]), "+f"(o[nb][1]), "+f"(o[nb][2]), "+f"(o[nb][3])
                    : "r"(pa[kb2][0]), "r"(pa[kb2][1]), "r"(pa[kb2][2]), "r"(pa[kb2][3]),
                      "r"(b0), "r"(b1));
            }
        }
    }

    float inv0 = 1.f / l0, inv1 = 1.f / l1;
    unsigned* z32 = (unsigned*)z;
    size_t zr0 = (((size_t)b * SEQ + row0) * DRES + h * 64) >> 1;
    size_t zr8 = zr0 + 4 * DRES;
    #pragma unroll
    for (int nb = 0; nb < 8; nb++) {
        int cp = (nb * 8 + 2 * t4) >> 1;
        z32[zr0 + cp] = packh2(o[nb][0] * inv0, o[nb][1] * inv0);
        z32[zr8 + cp] = packh2(o[nb][2] * inv1, o[nb][3] * inv1);
    }
}

// ---------------- launch --------------------------------------------------------
extern "C" void kernel_launch(void* const* d_in, const int* in_sizes, int n_in,
                              void* d_out, int out_size)
{
    const float* resid_pre = (const float*)d_in[0];
    const float* ln1_w     = (const float*)d_in[1];
    const float* ln1_b     = (const float*)d_in[2];
    const float* WQ        = (const float*)d_in[3];
    const float* bQ        = (const float*)d_in[4];
    const float* WK        = (const float*)d_in[5];
    const float* bK        = (const float*)d_in[6];
    const float* WV        = (const float*)d_in[7];
    const float* bV        = (const float*)d_in[8];
    const float* WO        = (const float*)d_in[9];
    const float* bO        = (const float*)d_in[10];
    const float* ln2_w     = (const float*)d_in[11];
    const float* ln2_b     = (const float*)d_in[12];
    const float* Win       = (const float*)d_in[13];
    const float* bin       = (const float*)d_in[14];
    const float* Wout      = (const float*)d_in[15];
    const float* bout      = (const float*)d_in[16];
    float* out = (float*)d_out;

    __half *xh, *qkvh, *zh, *mlph;
    float *rm, *bqkv;
    unsigned *Wqkvh, *WOh, *Winh, *Wouth;
    cudaGetSymbolAddress((void**)&xh,    g_xh);
    cudaGetSymbolAddress((void**)&qkvh,  g_qkvh);
    cudaGetSymbolAddress((void**)&zh,    g_zh);
    cudaGetSymbolAddress((void**)&mlph,  g_mlph);
    cudaGetSymbolAddress((void**)&rm,    g_rm);
    cudaGetSymbolAddress((void**)&bqkv,  g_bqkv);
    cudaGetSymbolAddress((void**)&Wqkvh, g_Wqkvh);
    cudaGetSymbolAddress((void**)&WOh,   g_WOh);
    cudaGetSymbolAddress((void**)&Winh,  g_Winh);
    cudaGetSymbolAddress((void**)&Wouth, g_Wouth);

    cudaFuncSetAttribute(hgemm_kernel,
                         cudaFuncAttributeMaxDynamicSharedMemorySize, SMEM_BYTES);

    // weight prep: repack QKV + pair-interleave all weights into fp16
    repackh_kernel<<<((DRES / 2) * D3) / 256, 256>>>(WQ, WK, WV, bQ, bK, bV);
    pairh4_kernel<<<((DRES / 2) * DRES / 4) / 256, 256>>>(
        WO, (uint4*)WOh, DRES, (DRES / 2) * DRES / 4);
    pairh4_kernel<<<((DRES / 2) * DMLP / 4) / 256, 256>>>(
        Win, (uint4*)Winh, DMLP, (DRES / 2) * DMLP / 4);
    pairh4_kernel<<<((DMLP / 2) * DRES / 4) / 256, 256>>>(
        Wout, (uint4*)Wouth, DRES, (DMLP / 2) * DRES / 4);

    // LN1 -> fp16
    lnh_kernel<<<T_TOK, 256>>>(resid_pre, ln1_w, ln1_b, xh);

    // QKV projection -> fp16 qkv
    hgemm_kernel<<<dim3(D3 / 128, T_TOK / 128), 256, SMEM_BYTES>>>(
        xh, Wqkvh, bqkv, nullptr, qkvh, T_TOK, D3, DRES, 0);

    // fp16 tensor-core causal flash attention
    attnh_kernel<<<dim3(SEQ / 128, NH, 2), 256>>>(qkvh, zh);

    // O projection + residual -> fp32 resid_mid (exact residual)
    hgemm_kernel<<<dim3(DRES / 128, T_TOK / 128), 256, SMEM_BYTES>>>(
        zh, WOh, bO, resid_pre, rm, T_TOK, DRES, DRES, 1);

    // LN2 -> fp16
    lnh_kernel<<<T_TOK, 256>>>(rm, ln2_w, ln2_b, xh);

    // MLP in + exact GELU -> fp16 hidden
    hgemm_kernel<<<dim3(DMLP / 128, T_TOK / 128), 256, SMEM_BYTES>>>(
        xh, Winh, bin, nullptr, mlph, T_TOK, DMLP, DRES, 2);

    // MLP out + residual -> final fp32 output
    hgemm_kernel<<<dim3(DRES / 128, T_TOK / 128), 256, SMEM_BYTES>>>(
        mlph, Wouth, bout, rm, out, T_TOK, DRES, DMLP, 1);
}

// round 16
// speedup vs baseline: 7.5225x; 1.0541x over previous
#include <cuda_runtime.h>
#include <cuda_fp16.h>
#include <math.h>

#define T_TOK 4096
#define SEQ   2048
#define DRES  1024
#define D3    3072
#define DMLP  4096
#define NH    16

// ---------------- device scratch ----------------------------------------------
__device__ __half  g_xh [(size_t)T_TOK * DRES];    // LN output (fp16)
__device__ __half  g_qkvh[(size_t)T_TOK * D3];     // QKV (fp16)
__device__ __half  g_zh [(size_t)T_TOK * DRES];    // attention out (fp16)
__device__ __half  g_mlph[(size_t)T_TOK * DMLP];   // MLP hidden post-gelu (fp16)
__device__ float   g_rm [(size_t)T_TOK * DRES];    // resid_mid (fp32, exact)
__device__ float    g_bqkv[D3];
__device__ unsigned g_Wqkvh[(size_t)(DRES / 2) * D3];   // pair-interleaved half2
__device__ unsigned g_WOh  [(size_t)(DRES / 2) * DRES];
__device__ unsigned g_Winh [(size_t)(DRES / 2) * DMLP];
__device__ unsigned g_Wouth[(size_t)(DMLP / 2) * DRES];

__device__ __forceinline__ unsigned packh2(float a, float b) {
    __half2 h = __floats2half2_rn(a, b);
    return *(unsigned*)&h;
}

// ---------------- weight converts (vectorized) ---------------------------------
__global__ __launch_bounds__(256) void pairh4_kernel(
    const float* __restrict__ W, uint4* __restrict__ Wp4, int N, int total4)
{
    int idx = blockIdx.x * 256 + threadIdx.x;
    if (idx >= total4) return;
    int N4 = N >> 2;
    int kp = idx / N4, n = (idx % N4) << 2;
    const float4 r0 = *(const float4*)(W + (size_t)(2 * kp) * N + n);
    const float4 r1 = *(const float4*)(W + (size_t)(2 * kp + 1) * N + n);
    uint4 o;
    o.x = packh2(r0.x, r1.x);
    o.y = packh2(r0.y, r1.y);
    o.z = packh2(r0.z, r1.z);
    o.w = packh2(r0.w, r1.w);
    Wp4[idx] = o;
}

// QKV weights: [h,d,e] x3 -> pair-interleaved half2 [512][3072]
__global__ __launch_bounds__(256) void repackh_kernel(
    const float* __restrict__ WQ, const float* __restrict__ WK,
    const float* __restrict__ WV, const float* __restrict__ bQ,
    const float* __restrict__ bK, const float* __restrict__ bV)
{
    int idx = blockIdx.x * 256 + threadIdx.x;
    if (idx < D3) {
        g_bqkv[idx] = (idx < 1024) ? bQ[idx]
                    : (idx < 2048) ? bK[idx - 1024]
                    :                bV[idx - 2048];
    }
    if (idx >= (DRES / 2) * D3) return;
    int kp = idx / D3;
    int j  = idx % D3;
    const float* W = WQ; int jj = j;
    if (j >= 2048)      { W = WV; jj = j - 2048; }
    else if (j >= 1024) { W = WK; jj = j - 1024; }
    int base = ((jj >> 6) << 16) | (jj & 63);
    g_Wqkvh[idx] = packh2(W[base + ((2 * kp) << 6)], W[base + ((2 * kp + 1) << 6)]);
}

// ---------------- layernorm: fp32 in, fp16 out ---------------------------------
__global__ __launch_bounds__(256) void lnh_kernel(
    const float* __restrict__ x, const float* __restrict__ w,
    const float* __restrict__ b, __half* __restrict__ y)
{
    __shared__ float red[8];
    __shared__ float sMean, sRstd;
    int row = blockIdx.x, tid = threadIdx.x;
    const float* xr = x + (size_t)row * DRES;
    float4 v = ((const float4*)xr)[tid];

    float s = v.x + v.y + v.z + v.w;
    #pragma unroll
    for (int o = 16; o > 0; o >>= 1) s += __shfl_xor_sync(0xffffffffu, s, o);
    if ((tid & 31) == 0) red[tid >> 5] = s;
    __syncthreads();
    if (tid == 0) {
        float t = 0.f;
        #pragma unroll
        for (int i = 0; i < 8; i++) t += red[i];
        sMean = t * (1.f / DRES);
    }
    __syncthreads();
    float mean = sMean;
    float cx = v.x - mean, cy = v.y - mean, cz = v.z - mean, cw = v.w - mean;
    float sq = cx * cx + cy * cy + cz * cz + cw * cw;
    #pragma unroll
    for (int o = 16; o > 0; o >>= 1) sq += __shfl_xor_sync(0xffffffffu, sq, o);
    if ((tid & 31) == 0) red[tid >> 5] = sq;
    __syncthreads();
    if (tid == 0) {
        float t = 0.f;
        #pragma unroll
        for (int i = 0; i < 8; i++) t += red[i];
        sRstd = rsqrtf(t * (1.f / DRES) + 1e-5f);
    }
    __syncthreads();
    float rstd = sRstd;
    float4 wv = ((const float4*)w)[tid];
    float4 bv = ((const float4*)b)[tid];
    unsigned* yo = (unsigned*)(y + (size_t)row * DRES);
    yo[2 * tid]     = packh2(cx * rstd * wv.x + bv.x, cy * rstd * wv.y + bv.y);
    yo[2 * tid + 1] = packh2(cz * rstd * wv.z + bv.z, cw * rstd * wv.w + bv.w);
}

// ---------------- FP16 tensor-core GEMM (unchanged from R13 — at HMMA peak) ----
__device__ __forceinline__ float gelu_exact(float x) {
    return 0.5f * x * (1.0f + erff(x * 0.70710678118654752f));
}

#define A_STRIDE 36
#define A_U32 (128 * A_STRIDE)
#define B_U32 (32 * 128)
#define STAGE_U32 (A_U32 + B_U32)
#define SMEM_BYTES (3 * STAGE_U32 * 4)

__device__ __forceinline__ void cp_async16(void* smem_dst, const void* gmem_src) {
    unsigned saddr = (unsigned)__cvta_generic_to_shared(smem_dst);
    asm volatile("cp.async.cg.shared.global [%0], [%1], 16;\n"
                 :: "r"(saddr), "l"(gmem_src));
}
__device__ __forceinline__ void ldsm4(unsigned r[4], unsigned saddr) {
    asm volatile(
        "ldmatrix.sync.aligned.m8n8.x4.shared.b16 {%0,%1,%2,%3}, [%4];"
        : "=r"(r[0]), "=r"(r[1]), "=r"(r[2]), "=r"(r[3]) : "r"(saddr));
}
__device__ __forceinline__ void ldsm4t(unsigned r[4], unsigned saddr) {
    asm volatile(
        "ldmatrix.sync.aligned.m8n8.x4.trans.shared.b16 {%0,%1,%2,%3}, [%4];"
        : "=r"(r[0]), "=r"(r[1]), "=r"(r[2]), "=r"(r[3]) : "r"(saddr));
}

__device__ __forceinline__ void load_stage_h(
    unsigned* As, unsigned* Bs,
    const unsigned* __restrict__ A32, const unsigned* __restrict__ Bp,
    int m0, int n0, int kt32, int K2, int N, int tid)
{
    #pragma unroll
    for (int u = 0; u < 4; u++) {
        int lin = u * 256 + tid;
        int m = lin >> 3, kq = lin & 7;
        cp_async16(As + m * A_STRIDE + kq * 4,
                   A32 + (size_t)(m0 + m) * K2 + kt32 + kq * 4);
    }
    #pragma unroll
    for (int u = 0; u < 4; u++) {
        int lin = u * 256 + tid;
        int kp = lin >> 5, nc = (lin & 31) * 4;
        int swz = nc ^ ((kp & 3) << 3);
        cp_async16(Bs + kp * 128 + swz,
                   Bp + (size_t)(kt32 + kp) * N + n0 + nc);
    }
}

__global__ __launch_bounds__(256, 2) void hgemm_kernel(
    const __half* __restrict__ A, const unsigned* __restrict__ Bp,
    const float* __restrict__ bias, const float* __restrict__ res,
    void* __restrict__ Cv, int M, int N, int K, int mode)
{
    extern __shared__ unsigned smem[];
    const unsigned* A32 = (const unsigned*)A;
    int tid = threadIdx.x;
    int lane = tid & 31;
    int warp = tid >> 5;
    int warp_m = warp & 1;
    int warp_n = warp >> 1;
    int m0 = blockIdx.y * 128, n0 = blockIdx.x * 128;
    int K2 = K >> 1;
    int t4 = lane & 3, g8 = lane >> 2;

    int lrow = warp_m * 64 + (lane & 7) + ((lane >> 3) & 1) * 8;
    int lcol = ((lane >> 4) & 1) * 4;
    unsigned sbase = (unsigned)__cvta_generic_to_shared(smem);
    unsigned aoff = (lrow * A_STRIDE + lcol) * 4;

    float c[4][4][4];
    #pragma unroll
    for (int i = 0; i < 4; i++)
        #pragma unroll
        for (int j = 0; j < 4; j++) {
            c[i][j][0] = 0.f; c[i][j][1] = 0.f; c[i][j][2] = 0.f; c[i][j][3] = 0.f;
        }

    int KT = K >> 6;

    load_stage_h(smem, smem + A_U32, A32, Bp, m0, n0, 0, K2, N, tid);
    asm volatile("cp.async.commit_group;\n");
    load_stage_h(smem + STAGE_U32, smem + STAGE_U32 + A_U32, A32, Bp,
                 m0, n0, 32, K2, N, tid);
    asm volatile("cp.async.commit_group;\n");

    for (int t = 0; t < KT; t++) {
        if (t + 2 < KT) {
            unsigned* Asn = smem + ((t + 2) % 3) * STAGE_U32;
            load_stage_h(Asn, Asn + A_U32, A32, Bp, m0, n0,
                         (t + 2) * 32, K2, N, tid);
        }
        asm volatile("cp.async.commit_group;\n");
        asm volatile("cp.async.wait_group 2;\n");
        __syncthreads();

        int buf = t % 3;
        const unsigned* Bs = smem + buf * STAGE_U32 + A_U32;
        unsigned abase = sbase + buf * (STAGE_U32 * 4) + aoff;

        #pragma unroll
        for (int ks = 0; ks < 4; ks++) {
            int kpb = ks * 8;
            unsigned a[4][4];
            #pragma unroll
            for (int mt = 0; mt < 4; mt++)
                ldsm4(a[mt], abase + (mt * 16 * A_STRIDE + kpb) * 4);
            unsigned bfr[4][2];
            #pragma unroll
            for (int nt = 0; nt < 4; nt++) {
                int n = warp_n * 32 + nt * 8 + g8;
                int swz = n ^ (t4 << 3);
                bfr[nt][0] = Bs[(kpb + t4) * 128 + swz];
                bfr[nt][1] = Bs[(kpb + t4 + 4) * 128 + swz];
            }
            #pragma unroll
            for (int mt = 0; mt < 4; mt++)
                #pragma unroll
                for (int nt = 0; nt < 4; nt++) {
                    asm volatile(
                        "mma.sync.aligned.m16n8k16.row.col.f32.f16.f16.f32 "
                        "{%0,%1,%2,%3}, {%4,%5,%6,%7}, {%8,%9}, {%0,%1,%2,%3};\n"
                        : "+f"(c[mt][nt][0]), "+f"(c[mt][nt][1]),
                          "+f"(c[mt][nt][2]), "+f"(c[mt][nt][3])
                        : "r"(a[mt][0]), "r"(a[mt][1]), "r"(a[mt][2]), "r"(a[mt][3]),
                          "r"(bfr[nt][0]), "r"(bfr[nt][1]));
                }
        }
        __syncthreads();
    }

    #pragma unroll
    for (int mt = 0; mt < 4; mt++) {
        int r0 = m0 + warp_m * 64 + mt * 16 + g8;
        #pragma unroll
        for (int nt = 0; nt < 4; nt++) {
            int col = n0 + warp_n * 32 + nt * 8 + 2 * t4;
            float2 bb = *(const float2*)(bias + col);
            float2 v0 = make_float2(c[mt][nt][0] + bb.x, c[mt][nt][1] + bb.y);
            float2 v1 = make_float2(c[mt][nt][2] + bb.x, c[mt][nt][3] + bb.y);
            if (mode == 1) {
                float* C = (float*)Cv;
                float2 ra = *(const float2*)(res + (size_t)r0 * N + col);
                float2 rb = *(const float2*)(res + (size_t)(r0 + 8) * N + col);
                v0.x += ra.x; v0.y += ra.y;
                v1.x += rb.x; v1.y += rb.y;
                *(float2*)(C + (size_t)r0 * N + col) = v0;
                *(float2*)(C + (size_t)(r0 + 8) * N + col) = v1;
            } else {
                if (mode == 2) {
                    v0.x = gelu_exact(v0.x); v0.y = gelu_exact(v0.y);
                    v1.x = gelu_exact(v1.x); v1.y = gelu_exact(v1.y);
                }
                unsigned* C = (unsigned*)Cv;
                C[((size_t)r0 * N + col) >> 1]       = packh2(v0.x, v0.y);
                C[((size_t)(r0 + 8) * N + col) >> 1] = packh2(v1.x, v1.y);
            }
        }
    }
}

// ---------------- fp16 TC flash attention: cp.async double-buffer + ldmatrix ---
// Br=128 (8 warps x 16 rows), Bc=64. K and V staged as straight row-major
// copies (2 buffers); K-frags via ldmatrix.x4, V-frags via ldmatrix.x4.trans.
#define KVP 36   // u32 per row (32 + 4 pad): conflict-free ldmatrix phases

__global__ __launch_bounds__(256) void attnh_kernel(
    const __half* __restrict__ qkv, __half* __restrict__ z)
{
    __shared__ unsigned Ks[2][64 * KVP];   // [key][dimpair]
    __shared__ unsigned Vs[2][64 * KVP];   // [key][dimpair]

    int q0 = (int)(gridDim.x - 1 - blockIdx.x) * 128;   // heavy blocks first
    int h  = blockIdx.y, b = blockIdx.z;
    int tid = threadIdx.x, lane = tid & 31, w = tid >> 5;
    int t4 = lane & 3, g8 = lane >> 2;

    const unsigned* qb32 = (const unsigned*)(qkv + (size_t)b * SEQ * D3) + h * 32;
    const unsigned* kb32 = qb32 + 512;
    const unsigned* vb32 = qb32 + 1024;
    const int RS = D3 / 2;

    int row0 = q0 + w * 16 + g8;

    // per-thread staging slots: key = tid>>2, two 16B chunks at (tid&3)*2
    int skey = tid >> 2;
    int skq  = (tid & 3) * 2;

    // ldmatrix base addresses (buffer 0; buffer 1 adds KVBUF bytes)
    unsigned kb0 = (unsigned)__cvta_generic_to_shared(&Ks[0][0]);
    unsigned vb0 = (unsigned)__cvta_generic_to_shared(&Vs[0][0]);
    const unsigned KVBUF = 64 * KVP * 4;
    unsigned krow = kb0 + ((lane & 7) * KVP) * 4 + (lane >> 3) * 16;
    unsigned vrow = vb0 + (lane * KVP) * 4;

    // Q fragments (scaled by 1/8)
    __half2 scale = __float2half2_rn(0.125f);
    unsigned qa[4][4];
    {
        const unsigned* r0p = qb32 + (size_t)row0 * RS;
        const unsigned* r8p = qb32 + (size_t)(row0 + 8) * RS;
        #pragma unroll
        for (int kb = 0; kb < 4; kb++) {
            int kp = kb * 8 + t4;
            __half2 x0 = __hmul2(*(const __half2*)&r0p[kp], scale);
            __half2 x1 = __hmul2(*(const __half2*)&r8p[kp], scale);
            __half2 x2 = __hmul2(*(const __half2*)&r0p[kp + 4], scale);
            __half2 x3 = __hmul2(*(const __half2*)&r8p[kp + 4], scale);
            qa[kb][0] = *(unsigned*)&x0;
            qa[kb][1] = *(unsigned*)&x1;
            qa[kb][2] = *(unsigned*)&x2;
            qa[kb][3] = *(unsigned*)&x3;
        }
    }

    float m0 = -1e30f, m1 = -1e30f, l0 = 0.f, l1 = 0.f;
    float o[8][4];
    #pragma unroll
    for (int nb = 0; nb < 8; nb++) {
        o[nb][0] = 0.f; o[nb][1] = 0.f; o[nb][2] = 0.f; o[nb][3] = 0.f;
    }

    int ntiles = (q0 >> 6) + 2;

    // prologue: stage tile 0 into buffer 0
    {
        const unsigned* ksrc = kb32 + (size_t)skey * RS + skq * 4;
        const unsigned* vsrc = vb32 + (size_t)skey * RS + skq * 4;
        unsigned* kdst = &Ks[0][skey * KVP + skq * 4];
        unsigned* vdst = &Vs[0][skey * KVP + skq * 4];
        cp_async16(kdst, ksrc);     cp_async16(kdst + 4, ksrc + 4);
        cp_async16(vdst, vsrc);     cp_async16(vdst + 4, vsrc + 4);
    }
    asm volatile("cp.async.commit_group;\n");

    for (int t = 0; t < ntiles; t++) {
        if (t + 1 < ntiles) {
            int j1 = (t + 1) * 64;
            int nbuf = (t + 1) & 1;
            const unsigned* ksrc = kb32 + (size_t)(j1 + skey) * RS + skq * 4;
            const unsigned* vsrc = vb32 + (size_t)(j1 + skey) * RS + skq * 4;
            unsigned* kdst = &Ks[nbuf][skey * KVP + skq * 4];
            unsigned* vdst = &Vs[nbuf][skey * KVP + skq * 4];
            cp_async16(kdst, ksrc); cp_async16(kdst + 4, ksrc + 4);
            cp_async16(vdst, vsrc); cp_async16(vdst + 4, vsrc + 4);
        }
        asm volatile("cp.async.commit_group;\n");
        asm volatile("cp.async.wait_group 1;\n");
        __syncthreads();

        int j0 = t * 64;
        int buf = t & 1;
        unsigned kbb = krow + buf * KVBUF;
        unsigned vbb = vrow + buf * KVBUF;

        // S = (Q/8) K^T : K-frags via ldmatrix.x4 (2 per n-block)
        float c[8][4];
        #pragma unroll
        for (int nb = 0; nb < 8; nb++) {
            unsigned kf[2][4];
            unsigned ka = kbb + nb * 8 * KVP * 4;
            ldsm4(kf[0], ka);
            ldsm4(kf[1], ka + 64);
            c[nb][0] = 0.f; c[nb][1] = 0.f; c[nb][2] = 0.f; c[nb][3] = 0.f;
            #pragma unroll
            for (int kb = 0; kb < 4; kb++) {
                unsigned b0 = kf[kb >> 1][(kb & 1) * 2];
                unsigned b1 = kf[kb >> 1][(kb & 1) * 2 + 1];
                asm volatile(
                    "mma.sync.aligned.m16n8k16.row.col.f32.f16.f16.f32 "
                    "{%0,%1,%2,%3}, {%4,%5,%6,%7}, {%8,%9}, {%0,%1,%2,%3};\n"
                    : "+f"(c[nb][0]), "+f"(c[nb][1]), "+f"(c[nb][2]), "+f"(c[nb][3])
                    : "r"(qa[kb][0]), "r"(qa[kb][1]), "r"(qa[kb][2]), "r"(qa[kb][3]),
                      "r"(b0), "r"(b1));
            }
        }

        // causal mask (near-diagonal tiles only)
        if (j0 + 63 > q0 + w * 16) {
            #pragma unroll
            for (int nb = 0; nb < 8; nb++) {
                int key = j0 + nb * 8 + 2 * t4;
                if (key > row0)         c[nb][0] = -1e30f;
                if (key + 1 > row0)     c[nb][1] = -1e30f;
                if (key > row0 + 8)     c[nb][2] = -1e30f;
                if (key + 1 > row0 + 8) c[nb][3] = -1e30f;
            }
        }

        // online softmax
        float mt0 = -1e30f, mt1 = -1e30f;
        #pragma unroll
        for (int nb = 0; nb < 8; nb++) {
            mt0 = fmaxf(mt0, fmaxf(c[nb][0], c[nb][1]));
            mt1 = fmaxf(mt1, fmaxf(c[nb][2], c[nb][3]));
        }
        mt0 = fmaxf(mt0, __shfl_xor_sync(0xffffffffu, mt0, 1));
        mt0 = fmaxf(mt0, __shfl_xor_sync(0xffffffffu, mt0, 2));
        mt1 = fmaxf(mt1, __shfl_xor_sync(0xffffffffu, mt1, 1));
        mt1 = fmaxf(mt1, __shfl_xor_sync(0xffffffffu, mt1, 2));

        float mn0 = fmaxf(m0, mt0), mn1 = fmaxf(m1, mt1);
        float al0 = __expf(m0 - mn0), al1 = __expf(m1 - mn1);
        m0 = mn0; m1 = mn1;

        float rs0 = 0.f, rs1 = 0.f;
        #pragma unroll
        for (int nb = 0; nb < 8; nb++) {
            c[nb][0] = __expf(c[nb][0] - mn0);
            c[nb][1] = __expf(c[nb][1] - mn0);
            c[nb][2] = __expf(c[nb][2] - mn1);
            c[nb][3] = __expf(c[nb][3] - mn1);
            rs0 += c[nb][0] + c[nb][1];
            rs1 += c[nb][2] + c[nb][3];
        }
        rs0 += __shfl_xor_sync(0xffffffffu, rs0, 1);
        rs0 += __shfl_xor_sync(0xffffffffu, rs0, 2);
        rs1 += __shfl_xor_sync(0xffffffffu, rs1, 1);
        rs1 += __shfl_xor_sync(0xffffffffu, rs1, 2);
        l0 = l0 * al0 + rs0;
        l1 = l1 * al1 + rs1;

        #pragma unroll
        for (int nb = 0; nb < 8; nb++) {
            o[nb][0] *= al0; o[nb][1] *= al0;
            o[nb][2] *= al1; o[nb][3] *= al1;
        }

        // pack P into fp16 a-fragments
        unsigned pa[4][4];
        #pragma unroll
        for (int kb2 = 0; kb2 < 4; kb2++) {
            pa[kb2][0] = packh2(c[2 * kb2][0],     c[2 * kb2][1]);
            pa[kb2][1] = packh2(c[2 * kb2][2],     c[2 * kb2][3]);
            pa[kb2][2] = packh2(c[2 * kb2 + 1][0], c[2 * kb2 + 1][1]);
            pa[kb2][3] = packh2(c[2 * kb2 + 1][2], c[2 * kb2 + 1][3]);
        }

        // O += P @ V : V-frags via ldmatrix.x4.trans (2 per n-block)
        #pragma unroll
        for (int nb = 0; nb < 8; nb++) {
            unsigned vf[2][4];
            ldsm4t(vf[0], vbb + nb * 16);
            ldsm4t(vf[1], vbb + 32 * KVP * 4 + nb * 16);
            #pragma unroll
            for (int kb2 = 0; kb2 < 4; kb2++) {
                unsigned b0 = vf[kb2 >> 1][(kb2 & 1) * 2];
                unsigned b1 = vf[kb2 >> 1][(kb2 & 1) * 2 + 1];
                asm volatile(
                    "mma.sync.aligned.m16n8k16.row.col.f32.f16.f16.f32 "
                    "{%0,%1,%2,%3}, {%4,%5,%6,%7}, {%8,%9}, {%0,%1,%2,%3};\n"
                    : "+f"(o[nb][0]), "+f"(o[nb][1]), "+f"(o[nb][2]), "+f"(o[nb][3])
                    : "r"(pa[kb2][0]), "r"(pa[kb2][1]), "r"(pa[kb2][2]), "r"(pa[kb2][3]),
                      "r"(b0), "r"(b1));
            }
        }
        __syncthreads();   // all warps done with buf before next-iter overwrite
    }

    float inv0 = 1.f / l0, inv1 = 1.f / l1;
    unsigned* z32 = (unsigned*)z;
    size_t zr0 = (((size_t)b * SEQ + row0) * DRES + h * 64) >> 1;
    size_t zr8 = zr0 + 4 * DRES;
    #pragma unroll
    for (int nb = 0; nb < 8; nb++) {
        int cp = (nb * 8 + 2 * t4) >> 1;
        z32[zr0 + cp] = packh2(o[nb][0] * inv0, o[nb][1] * inv0);
        z32[zr8 + cp] = packh2(o[nb][2] * inv1, o[nb][3] * inv1);
    }
}

// ---------------- launch --------------------------------------------------------
extern "C" void kernel_launch(void* const* d_in, const int* in_sizes, int n_in,
                              void* d_out, int out_size)
{
    const float* resid_pre = (const float*)d_in[0];
    const float* ln1_w     = (const float*)d_in[1];
    const float* ln1_b     = (const float*)d_in[2];
    const float* WQ        = (const float*)d_in[3];
    const float* bQ        = (const float*)d_in[4];
    const float* WK        = (const float*)d_in[5];
    const float* bK        = (const float*)d_in[6];
    const float* WV        = (const float*)d_in[7];
    const float* bV        = (const float*)d_in[8];
    const float* WO        = (const float*)d_in[9];
    const float* bO        = (const float*)d_in[10];
    const float* ln2_w     = (const float*)d_in[11];
    const float* ln2_b     = (const float*)d_in[12];
    const float* Win       = (const float*)d_in[13];
    const float* bin       = (const float*)d_in[14];
    const float* Wout      = (const float*)d_in[15];
    const float* bout      = (const float*)d_in[16];
    float* out = (float*)d_out;

    __half *xh, *qkvh, *zh, *mlph;
    float *rm, *bqkv;
    unsigned *Wqkvh, *WOh, *Winh, *Wouth;
    cudaGetSymbolAddress((void**)&xh,    g_xh);
    cudaGetSymbolAddress((void**)&qkvh,  g_qkvh);
    cudaGetSymbolAddress((void**)&zh,    g_zh);
    cudaGetSymbolAddress((void**)&mlph,  g_mlph);
    cudaGetSymbolAddress((void**)&rm,    g_rm);
    cudaGetSymbolAddress((void**)&bqkv,  g_bqkv);
    cudaGetSymbolAddress((void**)&Wqkvh, g_Wqkvh);
    cudaGetSymbolAddress((void**)&WOh,   g_WOh);
    cudaGetSymbolAddress((void**)&Winh,  g_Winh);
    cudaGetSymbolAddress((void**)&Wouth, g_Wouth);

    cudaFuncSetAttribute(hgemm_kernel,
                         cudaFuncAttributeMaxDynamicSharedMemorySize, SMEM_BYTES);

    // weight prep
    repackh_kernel<<<((DRES / 2) * D3) / 256, 256>>>(WQ, WK, WV, bQ, bK, bV);
    pairh4_kernel<<<((DRES / 2) * DRES / 4) / 256, 256>>>(
        WO, (uint4*)WOh, DRES, (DRES / 2) * DRES / 4);
    pairh4_kernel<<<((DRES / 2) * DMLP / 4) / 256, 256>>>(
        Win, (uint4*)Winh, DMLP, (DRES / 2) * DMLP / 4);
    pairh4_kernel<<<((DMLP / 2) * DRES / 4) / 256, 256>>>(
        Wout, (uint4*)Wouth, DRES, (DMLP / 2) * DRES / 4);

    // LN1 -> fp16
    lnh_kernel<<<T_TOK, 256>>>(resid_pre, ln1_w, ln1_b, xh);

    // QKV projection -> fp16 qkv
    hgemm_kernel<<<dim3(D3 / 128, T_TOK / 128), 256, SMEM_BYTES>>>(
        xh, Wqkvh, bqkv, nullptr, qkvh, T_TOK, D3, DRES, 0);

    // fp16 tensor-core causal flash attention
    attnh_kernel<<<dim3(SEQ / 128, NH, 2), 256>>>(qkvh, zh);

    // O projection + residual -> fp32 resid_mid (exact residual)
    hgemm_kernel<<<dim3(DRES / 128, T_TOK / 128), 256, SMEM_BYTES>>>(
        zh, WOh, bO, resid_pre, rm, T_TOK, DRES, DRES, 1);

    // LN2 -> fp16
    lnh_kernel<<<T_TOK, 256>>>(rm, ln2_w, ln2_b, xh);

    // MLP in + exact GELU -> fp16 hidden
    hgemm_kernel<<<dim3(DMLP / 128, T_TOK / 128), 256, SMEM_BYTES>>>(
        xh, Winh, bin, nullptr, mlph, T_TOK, DMLP, DRES, 2);

    // MLP out + residual -> final fp32 output
    hgemm_kernel<<<dim3(DRES / 128, T_TOK / 128), 256, SMEM_BYTES>>>(
        mlph, Wouth, bout, rm, out, T_TOK, DRES, DMLP, 1);
}